// round 1
// baseline (speedup 1.0000x reference)
#include <cuda_runtime.h>
#include <math.h>

#define BATCH 8192
#define DIN   1024
#define DZ    256
#define DH    256
#define DT    16

// ---------------- scratch (device globals: no allocation allowed) ----------
__device__ float g_mu_q   [BATCH * DZ];
__device__ float g_sigma_q[BATCH * DZ];
__device__ float g_sigma_p[BATCH * DZ];
__device__ float g_ti     [BATCH * DT];
__device__ float g_r1     [BATCH * DZ];
__device__ double g_acc[3];   // [0]=spatial sum, [1]=temporal sum, [2]=energy sum

// ---------------- helpers ---------------------------------------------------
__device__ __forceinline__ float sp_beta(float x, float beta, float invb) {
    float t = beta * x;
    if (t > 20.f) return x;                    // log1p(exp(t)) ~= t for t>20
    return log1pf(expf(t)) * invb;
}

// ---------------- generic tiled SGEMM: C[M,N] = A[M,K] * B[N,K]^T ------------
// BM=128, BN=64, BK=8, 256 threads, 8x4 per thread.
// EP: 0=store, 1=relu, 2=softplus(beta=1.2), 3=zhat (relu(acc)+aux0*aux1),
//     4=sigmoid + accumulate (aux0-o)^2 into g_acc[0]
// DUAL: accumulate a second A1*B1^T (same M,N,K) before the epilogue.
template<int EP, bool DUAL>
__global__ __launch_bounds__(256)
void sgemm_nt(const float* __restrict__ A0, const float* __restrict__ B0,
              const float* __restrict__ A1, const float* __restrict__ B1,
              float* __restrict__ C, int M, int N, int K,
              const float* __restrict__ aux0, const float* __restrict__ aux1)
{
    const int BM = 128, BN = 64, BK = 8;
    __shared__ float As[BK][BM];
    __shared__ float Bs[BK][BN];
    __shared__ float red[256];

    const int tid = threadIdx.x;
    const int tx = tid & 15;     // 0..15 -> column group (4 wide)
    const int ty = tid >> 4;     // 0..15 -> row group (8 tall)
    const int bx = blockIdx.x, by = blockIdx.y;

    const int arow = tid >> 1;         // 0..127
    const int acol = (tid & 1) * 4;    // 0 or 4
    const int brow = tid >> 2;         // 0..63
    const int bcol = (tid & 3) * 2;    // 0,2,4,6

    float acc[8][4];
#pragma unroll
    for (int i = 0; i < 8; i++)
#pragma unroll
        for (int j = 0; j < 4; j++) acc[i][j] = 0.f;

    const int npass = DUAL ? 2 : 1;
    for (int pass = 0; pass < npass; ++pass) {
        const float* Ap = (DUAL && pass) ? A1 : A0;
        const float* Bp = (DUAL && pass) ? B1 : B0;
        const float* aptr = Ap + (size_t)(by * BM + arow) * K + acol;
        const float* bptr = Bp + (size_t)(bx * BN + brow) * K + bcol;
        for (int k0 = 0; k0 < K; k0 += BK) {
            float4 a4 = *(const float4*)(aptr + k0);
            float2 b2 = *(const float2*)(bptr + k0);
            __syncthreads();
            As[acol + 0][arow] = a4.x;
            As[acol + 1][arow] = a4.y;
            As[acol + 2][arow] = a4.z;
            As[acol + 3][arow] = a4.w;
            Bs[bcol + 0][brow] = b2.x;
            Bs[bcol + 1][brow] = b2.y;
            __syncthreads();
#pragma unroll
            for (int k = 0; k < BK; k++) {
                float ra[8], rb[4];
                *(float4*)(ra)     = *(const float4*)&As[k][ty * 8];
                *(float4*)(ra + 4) = *(const float4*)&As[k][ty * 8 + 4];
                *(float4*)(rb)     = *(const float4*)&Bs[k][tx * 4];
#pragma unroll
                for (int i = 0; i < 8; i++)
#pragma unroll
                    for (int j = 0; j < 4; j++)
                        acc[i][j] = fmaf(ra[i], rb[j], acc[i][j]);
            }
        }
    }

    // -------- epilogue --------
    float lsum = 0.f;
    const int grow0 = by * BM + ty * 8;
    const int gcol0 = bx * BN + tx * 4;
#pragma unroll
    for (int i = 0; i < 8; i++) {
        size_t base = (size_t)(grow0 + i) * N + gcol0;
        float4 v;
        float* vp = &v.x;
#pragma unroll
        for (int j = 0; j < 4; j++) {
            float a = acc[i][j];
            float o;
            if (EP == 0)      o = a;
            else if (EP == 1) o = fmaxf(a, 0.f);
            else if (EP == 2) o = sp_beta(a, 1.2f, 1.f / 1.2f);
            else if (EP == 3) o = fmaxf(a, 0.f) + aux0[base + j] * aux1[base + j];
            else {            // EP==4: sigmoid + spatial loss term
                o = 1.f / (1.f + expf(-a));
                float d = aux0[base + j] - o;
                lsum += d * d;
            }
            vp[j] = o;
        }
        *(float4*)(C + base) = v;
    }

    if (EP == 4) {
        red[tid] = lsum;
        __syncthreads();
#pragma unroll
        for (int s = 128; s > 0; s >>= 1) {
            if (tid < s) red[tid] += red[tid + s];
            __syncthreads();
        }
        if (tid == 0) atomicAdd(&g_acc[0], (double)red[0]);
    }
}

// ---------------- ti = I_t @ W_i2t^T  [B,16], K=1024 ------------------------
__global__ __launch_bounds__(256)
void ti_kernel(const float* __restrict__ I_t, const float* __restrict__ W_i2t)
{
    const int R = 16, KC = 128;
    __shared__ float sI[R][KC + 1];
    __shared__ float sW[DT][KC + 1];
    const int tid = threadIdx.x;
    const int row0 = blockIdx.x * R;
    const int r = tid >> 4, t = tid & 15;
    float acc = 0.f;
    for (int kc = 0; kc < DIN; kc += KC) {
        __syncthreads();
        for (int idx = tid; idx < R * KC; idx += 256) {
            int rr = idx / KC, kk = idx % KC;
            sI[rr][kk] = I_t[(size_t)(row0 + rr) * DIN + kc + kk];
        }
        for (int idx = tid; idx < DT * KC; idx += 256) {
            int tt = idx / KC, kk = idx % KC;
            sW[tt][kk] = W_i2t[(size_t)tt * DIN + kc + kk];
        }
        __syncthreads();
#pragma unroll 8
        for (int k = 0; k < KC; k++)
            acc = fmaf(sI[r][k], sW[t][k], acc);
    }
    g_ti[(size_t)(row0 + r) * DT + t] = acc;
}

// ---------------- fused theta -> thresholds -> z (+ temporal & energy) ------
__global__ __launch_bounds__(256)
void z_kernel(const float* __restrict__ theta_m_1,  // [B,16]
              const float* __restrict__ W_vip2t,    // [16,256]
              const float* __restrict__ W_t2z,      // [256,16]
              const float* __restrict__ eps_z,      // [B,256]
              const float* __restrict__ zhat,       // [B,256] (already in d_out)
              float* __restrict__ z_out)            // [B,256]
{
    const int R = 16;
    __shared__ float sWv[DT][DZ + 1];
    __shared__ float sSp[R][DZ + 1];
    __shared__ float sTheta[R][DT + 1];
    __shared__ float red[256];

    const int tid = threadIdx.x;
    const int row0 = blockIdx.x * R;

    for (int idx = tid; idx < DT * DZ; idx += 256) {
        int t = idx >> 8, n = idx & 255;
        sWv[t][n] = fmaxf(W_vip2t[idx], 0.f);      // Positive parametrization
    }
    for (int idx = tid; idx < R * DZ; idx += 256) {
        int r = idx >> 8, n = idx & 255;
        sSp[r][n] = g_sigma_p[(size_t)(row0 + r) * DZ + n];
    }
    __syncthreads();

    // theta[r][t]
    {
        int r = tid >> 4, t = tid & 15;
        float dot = 0.f;
#pragma unroll 8
        for (int n = 0; n < DZ; n++)
            dot = fmaf(sSp[r][n], sWv[t][n], dot);
        size_t tix = (size_t)(row0 + r) * DT + t;
        float th_h = 0.5f * theta_m_1[tix] + 0.1f * g_ti[tix] - dot;
        float u = 0.5f * th_h;                     // softplus beta=0.5
        float sp = (u > 20.f) ? th_h : log1pf(expf(u)) * 2.0f;
        sTheta[r][t] = 0.001f * sp;
    }
    __syncthreads();

    const int n = tid;
    float wt[DT];
#pragma unroll
    for (int t = 0; t < DT; t++)
        wt[t] = fmaxf(W_t2z[(size_t)n * DT + t], 0.f);

    float e_sum = 0.f, t_sum = 0.f;
    for (int r = 0; r < R; r++) {
        float thr = 0.f;
#pragma unroll
        for (int t = 0; t < DT; t++)
            thr = fmaf(sTheta[r][t], wt[t], thr);
        thr *= 10.f;
        size_t idx = (size_t)(row0 + r) * DZ + n;
        float raw = fmaf(eps_z[idx], g_sigma_q[idx], g_mu_q[idx]);
        raw = fminf(fmaxf(raw, 0.f), 1.f);
        float zv = fmaxf(raw - thr, 0.f);
        z_out[idx] = zv;
        e_sum += zv;                               // |z| == z (z >= 0)
        float d = zv - zhat[idx];
        t_sum = fmaf(d, d, t_sum);
    }

    red[tid] = e_sum; __syncthreads();
#pragma unroll
    for (int s = 128; s > 0; s >>= 1) { if (tid < s) red[tid] += red[tid + s]; __syncthreads(); }
    if (tid == 0) atomicAdd(&g_acc[2], (double)red[0]);
    __syncthreads();
    red[tid] = t_sum; __syncthreads();
#pragma unroll
    for (int s = 128; s > 0; s >>= 1) { if (tid < s) red[tid] += red[tid + s]; __syncthreads(); }
    if (tid == 0) atomicAdd(&g_acc[1], (double)red[0]);
}

// ---------------- scalar setup / finalize -----------------------------------
__global__ void zero_acc_kernel() {
    if (threadIdx.x < 3) g_acc[threadIdx.x] = 0.0;
}

__global__ void finalize_kernel(float* __restrict__ out_scalars) {
    if (threadIdx.x == 0) {
        out_scalars[0] = (float)(g_acc[0] / (double)((size_t)BATCH * DIN));  // spatial
        out_scalars[1] = (float)(g_acc[1] / (double)((size_t)BATCH * DZ));   // temporal
        out_scalars[2] = (float)(g_acc[2] / (double)((size_t)BATCH * DZ));   // energy
    }
}

// ---------------- launch -----------------------------------------------------
extern "C" void kernel_launch(void* const* d_in, const int* in_sizes, int n_in,
                              void* d_out, int out_size)
{
    const float* I_t        = (const float*)d_in[0];
    const float* h_m_1      = (const float*)d_in[1];
    const float* z_m_1      = (const float*)d_in[2];
    const float* theta_m_1  = (const float*)d_in[3];
    const float* eps_z      = (const float*)d_in[4];
    const float* eps_zhat   = (const float*)d_in[5];
    const float* W_post_mu  = (const float*)d_in[6];
    const float* W_post_lv  = (const float*)d_in[7];
    const float* W_z2h      = (const float*)d_in[8];
    const float* W_h2h      = (const float*)d_in[9];
    const float* W_prior_mu = (const float*)d_in[10];
    const float* W_prior_lv = (const float*)d_in[11];
    const float* W_i2t      = (const float*)d_in[12];
    const float* W_vip2t    = (const float*)d_in[13];
    const float* W_t2z      = (const float*)d_in[14];
    const float* W_rec1     = (const float*)d_in[15];
    const float* W_rec2     = (const float*)d_in[16];

    float* out       = (float*)d_out;
    float* out_ihat  = out;
    float* out_z     = out + (size_t)BATCH * DIN;
    float* out_h     = out_z + (size_t)BATCH * DZ;
    float* out_zhat  = out_h + (size_t)BATCH * DH;
    float* out_scal  = out_zhat + (size_t)BATCH * DZ;

    float *mu_q, *sigma_q, *sigma_p, *r1;
    cudaGetSymbolAddress((void**)&mu_q,    g_mu_q);
    cudaGetSymbolAddress((void**)&sigma_q, g_sigma_q);
    cudaGetSymbolAddress((void**)&sigma_p, g_sigma_p);
    cudaGetSymbolAddress((void**)&r1,      g_r1);

    const dim3 blk(256);
    const dim3 grid_n256(DZ / 64, BATCH / 128);   // (4, 64)
    const dim3 grid_n1024(DIN / 64, BATCH / 128); // (16, 64)

    zero_acc_kernel<<<1, 32>>>();

    // mu_q = relu(I_t @ W_post_mu^T),  sigma_q = relu(I_t @ W_post_lv^T)
    sgemm_nt<1, false><<<grid_n256, blk>>>(I_t, W_post_mu, nullptr, nullptr,
                                           mu_q, BATCH, DZ, DIN, nullptr, nullptr);
    sgemm_nt<1, false><<<grid_n256, blk>>>(I_t, W_post_lv, nullptr, nullptr,
                                           sigma_q, BATCH, DZ, DIN, nullptr, nullptr);
    // ti = I_t @ W_i2t^T
    ti_kernel<<<BATCH / 16, blk>>>(I_t, W_i2t);

    // sigma_p = softplus_beta(h_m_1 @ W_prior_lv^T, 1.2)
    sgemm_nt<2, false><<<grid_n256, blk>>>(h_m_1, W_prior_lv, nullptr, nullptr,
                                           sigma_p, BATCH, DZ, DH, nullptr, nullptr);
    // z_hat = relu(h_m_1 @ W_prior_mu^T) + eps_zhat * sigma_p
    sgemm_nt<3, false><<<grid_n256, blk>>>(h_m_1, W_prior_mu, nullptr, nullptr,
                                           out_zhat, BATCH, DZ, DH, eps_zhat, sigma_p);
    // h = relu(z_m_1 @ W_z2h^T + h_m_1 @ W_h2h^T)
    sgemm_nt<1, true><<<grid_n256, blk>>>(z_m_1, W_z2h, h_m_1, W_h2h,
                                          out_h, BATCH, DH, DZ, nullptr, nullptr);
    // theta -> thresholds -> z  (+ temporal, energy sums)
    z_kernel<<<BATCH / 16, blk>>>(theta_m_1, W_vip2t, W_t2z, eps_z, out_zhat, out_z);

    // r1 = z @ W_rec1^T
    sgemm_nt<0, false><<<grid_n256, blk>>>(out_z, W_rec1, nullptr, nullptr,
                                           r1, BATCH, DZ, DZ, nullptr, nullptr);
    // I_hat = sigmoid(r1 @ W_rec2^T)  (+ spatial sum vs I_t)
    sgemm_nt<4, false><<<grid_n1024, blk>>>(r1, W_rec2, nullptr, nullptr,
                                            out_ihat, BATCH, DIN, DZ, I_t, nullptr);

    finalize_kernel<<<1, 32>>>(out_scal);
    (void)in_sizes; (void)n_in; (void)out_size;
}

// round 3
// speedup vs baseline: 1.6747x; 1.6747x over previous
#include <cuda_runtime.h>
#include <cuda_bf16.h>
#include <mma.h>
#include <math.h>
#include <stdint.h>

using namespace nvcuda;

#define BATCH 8192
#define DIN   1024
#define DZ    256
#define DH    256
#define DT    16
#define DREC  256

// ---------------- scratch (device globals: no allocation allowed) ----------
__device__ float g_mu_q   [BATCH * DZ];
__device__ float g_sigma_q[BATCH * DZ];
__device__ float g_sigma_p[BATCH * DZ];
__device__ float g_ti     [BATCH * DT];
__device__ double g_acc[3];   // [0]=spatial, [1]=temporal, [2]=energy

// bf16 hi/lo copies of GEMM operands
__device__ __nv_bfloat16 g_It_hi [BATCH * DIN], g_It_lo [BATCH * DIN];
__device__ __nv_bfloat16 g_h_hi  [BATCH * DH],  g_h_lo  [BATCH * DH];
__device__ __nv_bfloat16 g_zm_hi [BATCH * DZ],  g_zm_lo [BATCH * DZ];
__device__ __nv_bfloat16 g_z_hi  [BATCH * DZ],  g_z_lo  [BATCH * DZ];
__device__ __nv_bfloat16 g_r1_hi [BATCH * DREC], g_r1_lo[BATCH * DREC];
__device__ __nv_bfloat16 g_Wpmu_hi [DZ * DIN],  g_Wpmu_lo [DZ * DIN];
__device__ __nv_bfloat16 g_Wplv_hi [DZ * DIN],  g_Wplv_lo [DZ * DIN];
__device__ __nv_bfloat16 g_Wz2h_hi [DH * DZ],   g_Wz2h_lo [DH * DZ];
__device__ __nv_bfloat16 g_Wh2h_hi [DH * DH],   g_Wh2h_lo [DH * DH];
__device__ __nv_bfloat16 g_Wprmu_hi[DZ * DH],   g_Wprmu_lo[DZ * DH];
__device__ __nv_bfloat16 g_Wprlv_hi[DZ * DH],   g_Wprlv_lo[DZ * DH];
__device__ __nv_bfloat16 g_Wi2t_hi [DT * DIN],  g_Wi2t_lo [DT * DIN];
__device__ __nv_bfloat16 g_Wr1_hi  [DREC * DZ], g_Wr1_lo  [DREC * DZ];
__device__ __nv_bfloat16 g_Wr2_hi  [DIN * DREC], g_Wr2_lo [DIN * DREC];

// ---------------- helpers ----------------------------------------------------
__device__ __forceinline__ float sp_beta(float x, float beta, float invb) {
    float t = beta * x;
    if (t > 20.f) return x;
    return log1pf(expf(t)) * invb;
}

// ---------------- fp32 -> bf16 hi/lo conversion ------------------------------
__global__ __launch_bounds__(256)
void cvt_kernel(const float4* __restrict__ in,
                uint2* __restrict__ hi2, uint2* __restrict__ lo2, int n4)
{
    int i = blockIdx.x * blockDim.x + threadIdx.x;
    if (i >= n4) return;
    float4 v = in[i];
    __nv_bfloat162 h0 = __float22bfloat162_rn(make_float2(v.x, v.y));
    __nv_bfloat162 h1 = __float22bfloat162_rn(make_float2(v.z, v.w));
    float2 f0 = __bfloat1622float2(h0);
    float2 f1 = __bfloat1622float2(h1);
    __nv_bfloat162 l0 = __float22bfloat162_rn(make_float2(v.x - f0.x, v.y - f0.y));
    __nv_bfloat162 l1 = __float22bfloat162_rn(make_float2(v.z - f1.x, v.w - f1.y));
    uint2 hv, lv;
    hv.x = *(uint32_t*)&h0; hv.y = *(uint32_t*)&h1;
    lv.x = *(uint32_t*)&l0; lv.y = *(uint32_t*)&l1;
    hi2[i] = hv;
    lo2[i] = lv;
}

// ============================================================================
// WMMA bf16 GEMM with hi/lo split: C[M,N] = A[M,K] @ B[N,K]^T   (fp32 accurate)
// BM=128, BN in {64,16}, BK=32, 256 threads.
// EP: 0=store, 1=relu, 2=softplus(1.2), 3=relu+aux0*aux1,
//     4=sigmoid + spatial loss vs aux0, 5=emit bf16 hi/lo (no fp32 store)
// ============================================================================
template<int EP, int BN, bool DUAL>
__global__ __launch_bounds__(256)
void tc_gemm(const __nv_bfloat16* __restrict__ A0h, const __nv_bfloat16* __restrict__ A0l,
             const __nv_bfloat16* __restrict__ B0h, const __nv_bfloat16* __restrict__ B0l, int K0,
             const __nv_bfloat16* __restrict__ A1h, const __nv_bfloat16* __restrict__ A1l,
             const __nv_bfloat16* __restrict__ B1h, const __nv_bfloat16* __restrict__ B1l, int K1,
             float* __restrict__ C, int N,
             const float* __restrict__ aux0, const float* __restrict__ aux1,
             __nv_bfloat16* __restrict__ Chi, __nv_bfloat16* __restrict__ Clo)
{
    constexpr int BM = 128, BK = 32, P = 40;   // P: smem pitch (bf16 elems), 80B
    constexpr int WARPS_M = (BN == 64) ? 4 : 8;
    constexpr int WM = BM / WARPS_M;           // 32 or 16
    constexpr int WN = (BN == 64) ? 32 : 16;
    constexpr int TM = WM / 16, TN = WN / 16;

    constexpr int TILE_BYTES = (2 * BM + 2 * BN) * P * 2;
    constexpr int C_BYTES = BM * BN * 4;
    constexpr int SMEM_BYTES = (TILE_BYTES > C_BYTES) ? TILE_BYTES : C_BYTES;

    __shared__ __align__(16) char sm_raw[SMEM_BYTES];
    __shared__ float red[256];

    __nv_bfloat16* sAh = (__nv_bfloat16*)sm_raw;
    __nv_bfloat16* sAl = sAh + BM * P;
    __nv_bfloat16* sBh = sAl + BM * P;
    __nv_bfloat16* sBl = sBh + BN * P;
    float* sC = (float*)sm_raw;

    const int tid = threadIdx.x;
    const int wid = tid >> 5;
    const int bx = blockIdx.x, by = blockIdx.y;
    const int wm = (BN == 64) ? (wid >> 1) : wid;
    const int wn = (BN == 64) ? (wid & 1) : 0;

    wmma::fragment<wmma::accumulator, 16, 16, 16, float> acc[TM][TN];
#pragma unroll
    for (int tm = 0; tm < TM; ++tm)
#pragma unroll
        for (int tn = 0; tn < TN; ++tn)
            wmma::fill_fragment(acc[tm][tn], 0.f);

    const int nsrc = DUAL ? 2 : 1;
    bool first = true;
    for (int src = 0; src < nsrc; ++src) {
        const __nv_bfloat16* Ah = src ? A1h : A0h;
        const __nv_bfloat16* Al = src ? A1l : A0l;
        const __nv_bfloat16* Bh = src ? B1h : B0h;
        const __nv_bfloat16* Bl = src ? B1l : B0l;
        const int K = src ? K1 : K0;

        for (int kc = 0; kc < K; kc += BK) {
            if (!first) __syncthreads();
            first = false;
            // ---- load A chunk: 128x32 bf16 (hi+lo), uint4 = 8 bf16 ----
            {
                // 512 uint4 per matrix, 2 per thread
#pragma unroll
                for (int it = 0; it < 2; ++it) {
                    int i = tid + it * 256;
                    int row = i >> 2, kq = i & 3;
                    const uint4* sh = (const uint4*)(Ah + (size_t)(by * BM + row) * K + kc + kq * 8);
                    const uint4* sl = (const uint4*)(Al + (size_t)(by * BM + row) * K + kc + kq * 8);
                    *(uint4*)(sAh + row * P + kq * 8) = *sh;
                    *(uint4*)(sAl + row * P + kq * 8) = *sl;
                }
            }
            // ---- load B chunk: BN x 32 ----
            {
                int nv = (BN * BK) / 8;       // 256 or 64 uint4
                if (BN == 64 || tid < nv) {
                    int row = tid >> 2, kq = tid & 3;
                    const uint4* sh = (const uint4*)(Bh + (size_t)(bx * BN + row) * K + kc + kq * 8);
                    const uint4* sl = (const uint4*)(Bl + (size_t)(bx * BN + row) * K + kc + kq * 8);
                    *(uint4*)(sBh + row * P + kq * 8) = *sh;
                    *(uint4*)(sBl + row * P + kq * 8) = *sl;
                }
            }
            __syncthreads();

            // ---- compute: 2 k-steps of 16 ----
#pragma unroll
            for (int ks = 0; ks < 2; ++ks) {
                wmma::fragment<wmma::matrix_a, 16, 16, 16, __nv_bfloat16, wmma::row_major> ah[TM], al[TM];
                wmma::fragment<wmma::matrix_b, 16, 16, 16, __nv_bfloat16, wmma::col_major> bh[TN], bl[TN];
#pragma unroll
                for (int tm = 0; tm < TM; ++tm) {
                    const __nv_bfloat16* p = sAh + (wm * WM + tm * 16) * P + ks * 16;
                    wmma::load_matrix_sync(ah[tm], p, P);
                    wmma::load_matrix_sync(al[tm], p + (sAl - sAh), P);
                }
#pragma unroll
                for (int tn = 0; tn < TN; ++tn) {
                    const __nv_bfloat16* p = sBh + (wn * WN + tn * 16) * P + ks * 16;
                    wmma::load_matrix_sync(bh[tn], p, P);
                    wmma::load_matrix_sync(bl[tn], p + (sBl - sBh), P);
                }
#pragma unroll
                for (int tm = 0; tm < TM; ++tm)
#pragma unroll
                    for (int tn = 0; tn < TN; ++tn) {
                        wmma::mma_sync(acc[tm][tn], ah[tm], bh[tn], acc[tm][tn]);
                        wmma::mma_sync(acc[tm][tn], ah[tm], bl[tn], acc[tm][tn]);
                        wmma::mma_sync(acc[tm][tn], al[tm], bh[tn], acc[tm][tn]);
                    }
            }
        }
    }

    // ---- stage C to smem ----
    __syncthreads();
#pragma unroll
    for (int tm = 0; tm < TM; ++tm)
#pragma unroll
        for (int tn = 0; tn < TN; ++tn)
            wmma::store_matrix_sync(sC + (wm * WM + tm * 16) * BN + wn * WN + tn * 16,
                                    acc[tm][tn], BN, wmma::mem_row_major);
    __syncthreads();

    // ---- epilogue ----
    float lsum = 0.f;
    if (BN == 64) {
        const int tx = tid & 15, ty = tid >> 4;
        const int gcol0 = bx * 64 + tx * 4;
#pragma unroll
        for (int i = 0; i < 8; ++i) {
            int row = ty * 8 + i;
            size_t gbase = (size_t)(by * BM + row) * N + gcol0;
            float4 v = *(const float4*)(sC + row * BN + tx * 4);
            float* vp = &v.x;
            float4 a0, a1;
            if (EP == 3) { a0 = *(const float4*)(aux0 + gbase); a1 = *(const float4*)(aux1 + gbase); }
            if (EP == 4) { a0 = *(const float4*)(aux0 + gbase); }
            const float* a0p = &a0.x; const float* a1p = &a1.x;
            float4 o; float* op = &o.x;
#pragma unroll
            for (int jj = 0; jj < 4; ++jj) {
                float a = vp[jj];
                float ov;
                if (EP == 0)      ov = a;
                else if (EP == 1) ov = fmaxf(a, 0.f);
                else if (EP == 2) ov = sp_beta(a, 1.2f, 1.f / 1.2f);
                else if (EP == 3) ov = fmaxf(a, 0.f) + a0p[jj] * a1p[jj];
                else if (EP == 4) { ov = 1.f / (1.f + expf(-a)); float dd = a0p[jj] - ov; lsum += dd * dd; }
                else              ov = a;   // EP==5
                op[jj] = ov;
            }
            if (EP == 5) {
                __nv_bfloat162 h0 = __float22bfloat162_rn(make_float2(o.x, o.y));
                __nv_bfloat162 h1 = __float22bfloat162_rn(make_float2(o.z, o.w));
                float2 f0 = __bfloat1622float2(h0);
                float2 f1 = __bfloat1622float2(h1);
                __nv_bfloat162 l0 = __float22bfloat162_rn(make_float2(o.x - f0.x, o.y - f0.y));
                __nv_bfloat162 l1 = __float22bfloat162_rn(make_float2(o.z - f1.x, o.w - f1.y));
                *(uint32_t*)(Chi + gbase)     = *(uint32_t*)&h0;
                *(uint32_t*)(Chi + gbase + 2) = *(uint32_t*)&h1;
                *(uint32_t*)(Clo + gbase)     = *(uint32_t*)&l0;
                *(uint32_t*)(Clo + gbase + 2) = *(uint32_t*)&l1;
            } else {
                *(float4*)(C + gbase) = o;
            }
        }
    } else {  // BN == 16, EP == 0 (ti)
        int row = tid >> 1, c0 = (tid & 1) * 8;
        size_t gbase = (size_t)(by * BM + row) * N + c0;
        *(float4*)(C + gbase)     = *(const float4*)(sC + row * 16 + c0);
        *(float4*)(C + gbase + 4) = *(const float4*)(sC + row * 16 + c0 + 4);
    }

    if (EP == 4) {
        red[tid] = lsum;
        __syncthreads();
#pragma unroll
        for (int s = 128; s > 0; s >>= 1) {
            if (tid < s) red[tid] += red[tid + s];
            __syncthreads();
        }
        if (tid == 0) atomicAdd(&g_acc[0], (double)red[0]);
    }
}

// ---------------- fused theta -> thresholds -> z (+ temporal & energy) ------
__global__ __launch_bounds__(256)
void z_kernel(const float* __restrict__ theta_m_1,
              const float* __restrict__ W_vip2t,
              const float* __restrict__ W_t2z,
              const float* __restrict__ eps_z,
              const float* __restrict__ zhat,
              float* __restrict__ z_out)
{
    const int R = 16;
    __shared__ float sWv[DT][DZ + 1];
    __shared__ float sSp[R][DZ + 1];
    __shared__ float sTheta[R][DT + 1];
    __shared__ float red[256];

    const int tid = threadIdx.x;
    const int row0 = blockIdx.x * R;

    for (int idx = tid; idx < DT * DZ; idx += 256) {
        int t = idx >> 8, n = idx & 255;
        sWv[t][n] = fmaxf(W_vip2t[idx], 0.f);
    }
    for (int idx = tid; idx < R * DZ; idx += 256) {
        int r = idx >> 8, n = idx & 255;
        sSp[r][n] = g_sigma_p[(size_t)(row0 + r) * DZ + n];
    }
    __syncthreads();

    {
        int r = tid >> 4, t = tid & 15;
        float dot = 0.f;
#pragma unroll 8
        for (int n = 0; n < DZ; n++)
            dot = fmaf(sSp[r][n], sWv[t][n], dot);
        size_t tix = (size_t)(row0 + r) * DT + t;
        float th_h = 0.5f * theta_m_1[tix] + 0.1f * g_ti[tix] - dot;
        float u = 0.5f * th_h;
        float sp = (u > 20.f) ? th_h : log1pf(expf(u)) * 2.0f;
        sTheta[r][t] = 0.001f * sp;
    }
    __syncthreads();

    const int n = tid;
    float wt[DT];
#pragma unroll
    for (int t = 0; t < DT; t++)
        wt[t] = fmaxf(W_t2z[(size_t)n * DT + t], 0.f);

    float e_sum = 0.f, t_sum = 0.f;
    for (int r = 0; r < R; r++) {
        float thr = 0.f;
#pragma unroll
        for (int t = 0; t < DT; t++)
            thr = fmaf(sTheta[r][t], wt[t], thr);
        thr *= 10.f;
        size_t idx = (size_t)(row0 + r) * DZ + n;
        float raw = fmaf(eps_z[idx], g_sigma_q[idx], g_mu_q[idx]);
        raw = fminf(fmaxf(raw, 0.f), 1.f);
        float zv = fmaxf(raw - thr, 0.f);
        z_out[idx] = zv;
        // bf16 hi/lo for rec1 GEMM
        __nv_bfloat16 h = __float2bfloat16_rn(zv);
        g_z_hi[idx] = h;
        g_z_lo[idx] = __float2bfloat16_rn(zv - __bfloat162float(h));
        e_sum += zv;
        float d = zv - zhat[idx];
        t_sum = fmaf(d, d, t_sum);
    }

    red[tid] = e_sum; __syncthreads();
#pragma unroll
    for (int s = 128; s > 0; s >>= 1) { if (tid < s) red[tid] += red[tid + s]; __syncthreads(); }
    if (tid == 0) atomicAdd(&g_acc[2], (double)red[0]);
    __syncthreads();
    red[tid] = t_sum; __syncthreads();
#pragma unroll
    for (int s = 128; s > 0; s >>= 1) { if (tid < s) red[tid] += red[tid + s]; __syncthreads(); }
    if (tid == 0) atomicAdd(&g_acc[1], (double)red[0]);
}

// ---------------- scalar setup / finalize -----------------------------------
__global__ void zero_acc_kernel() {
    if (threadIdx.x < 3) g_acc[threadIdx.x] = 0.0;
}

__global__ void finalize_kernel(float* __restrict__ out_scalars) {
    if (threadIdx.x == 0) {
        out_scalars[0] = (float)(g_acc[0] / (double)((size_t)BATCH * DIN));
        out_scalars[1] = (float)(g_acc[1] / (double)((size_t)BATCH * DZ));
        out_scalars[2] = (float)(g_acc[2] / (double)((size_t)BATCH * DZ));
    }
}

// ---------------- launch -----------------------------------------------------
static inline void cvt(const float* src, __nv_bfloat16* hi, __nv_bfloat16* lo, int n) {
    int n4 = n / 4;
    cvt_kernel<<<(n4 + 255) / 256, 256>>>((const float4*)src, (uint2*)hi, (uint2*)lo, n4);
}

extern "C" void kernel_launch(void* const* d_in, const int* in_sizes, int n_in,
                              void* d_out, int out_size)
{
    const float* I_t        = (const float*)d_in[0];
    const float* h_m_1      = (const float*)d_in[1];
    const float* z_m_1      = (const float*)d_in[2];
    const float* theta_m_1  = (const float*)d_in[3];
    const float* eps_z      = (const float*)d_in[4];
    const float* eps_zhat   = (const float*)d_in[5];
    const float* W_post_mu  = (const float*)d_in[6];
    const float* W_post_lv  = (const float*)d_in[7];
    const float* W_z2h      = (const float*)d_in[8];
    const float* W_h2h      = (const float*)d_in[9];
    const float* W_prior_mu = (const float*)d_in[10];
    const float* W_prior_lv = (const float*)d_in[11];
    const float* W_i2t      = (const float*)d_in[12];
    const float* W_vip2t    = (const float*)d_in[13];
    const float* W_t2z      = (const float*)d_in[14];
    const float* W_rec1     = (const float*)d_in[15];
    const float* W_rec2     = (const float*)d_in[16];

    float* out       = (float*)d_out;
    float* out_ihat  = out;
    float* out_z     = out + (size_t)BATCH * DIN;
    float* out_h     = out_z + (size_t)BATCH * DZ;
    float* out_zhat  = out_h + (size_t)BATCH * DH;
    float* out_scal  = out_zhat + (size_t)BATCH * DZ;

    // symbol addresses
    float *mu_q, *sigma_q, *sigma_p, *ti;
    cudaGetSymbolAddress((void**)&mu_q,    g_mu_q);
    cudaGetSymbolAddress((void**)&sigma_q, g_sigma_q);
    cudaGetSymbolAddress((void**)&sigma_p, g_sigma_p);
    cudaGetSymbolAddress((void**)&ti,      g_ti);
    __nv_bfloat16 *It_h, *It_l, *h_h, *h_l, *zm_h, *zm_l, *z_h, *z_l, *r1_h, *r1_l;
    __nv_bfloat16 *Wpmu_h, *Wpmu_l, *Wplv_h, *Wplv_l, *Wz2h_h, *Wz2h_l, *Wh2h_h, *Wh2h_l;
    __nv_bfloat16 *Wprmu_h, *Wprmu_l, *Wprlv_h, *Wprlv_l, *Wi2t_h, *Wi2t_l;
    __nv_bfloat16 *Wr1_h, *Wr1_l, *Wr2_h, *Wr2_l;
    cudaGetSymbolAddress((void**)&It_h, g_It_hi);   cudaGetSymbolAddress((void**)&It_l, g_It_lo);
    cudaGetSymbolAddress((void**)&h_h,  g_h_hi);    cudaGetSymbolAddress((void**)&h_l,  g_h_lo);
    cudaGetSymbolAddress((void**)&zm_h, g_zm_hi);   cudaGetSymbolAddress((void**)&zm_l, g_zm_lo);
    cudaGetSymbolAddress((void**)&z_h,  g_z_hi);    cudaGetSymbolAddress((void**)&z_l,  g_z_lo);
    cudaGetSymbolAddress((void**)&r1_h, g_r1_hi);   cudaGetSymbolAddress((void**)&r1_l, g_r1_lo);
    cudaGetSymbolAddress((void**)&Wpmu_h, g_Wpmu_hi);   cudaGetSymbolAddress((void**)&Wpmu_l, g_Wpmu_lo);
    cudaGetSymbolAddress((void**)&Wplv_h, g_Wplv_hi);   cudaGetSymbolAddress((void**)&Wplv_l, g_Wplv_lo);
    cudaGetSymbolAddress((void**)&Wz2h_h, g_Wz2h_hi);   cudaGetSymbolAddress((void**)&Wz2h_l, g_Wz2h_lo);
    cudaGetSymbolAddress((void**)&Wh2h_h, g_Wh2h_hi);   cudaGetSymbolAddress((void**)&Wh2h_l, g_Wh2h_lo);
    cudaGetSymbolAddress((void**)&Wprmu_h, g_Wprmu_hi); cudaGetSymbolAddress((void**)&Wprmu_l, g_Wprmu_lo);
    cudaGetSymbolAddress((void**)&Wprlv_h, g_Wprlv_hi); cudaGetSymbolAddress((void**)&Wprlv_l, g_Wprlv_lo);
    cudaGetSymbolAddress((void**)&Wi2t_h, g_Wi2t_hi);   cudaGetSymbolAddress((void**)&Wi2t_l, g_Wi2t_lo);
    cudaGetSymbolAddress((void**)&Wr1_h, g_Wr1_hi);     cudaGetSymbolAddress((void**)&Wr1_l, g_Wr1_lo);
    cudaGetSymbolAddress((void**)&Wr2_h, g_Wr2_hi);     cudaGetSymbolAddress((void**)&Wr2_l, g_Wr2_lo);

    const dim3 blk(256);
    const dim3 g256(DZ / 64, BATCH / 128);    // (4, 64)
    const dim3 g1024(DIN / 64, BATCH / 128);  // (16, 64)
    const dim3 g16(1, BATCH / 128);           // (1, 64)

    zero_acc_kernel<<<1, 32>>>();

    // --- conversions ---
    cvt(I_t,        It_h,   It_l,   BATCH * DIN);
    cvt(h_m_1,      h_h,    h_l,    BATCH * DH);
    cvt(z_m_1,      zm_h,   zm_l,   BATCH * DZ);
    cvt(W_post_mu,  Wpmu_h, Wpmu_l, DZ * DIN);
    cvt(W_post_lv,  Wplv_h, Wplv_l, DZ * DIN);
    cvt(W_z2h,      Wz2h_h, Wz2h_l, DH * DZ);
    cvt(W_h2h,      Wh2h_h, Wh2h_l, DH * DH);
    cvt(W_prior_mu, Wprmu_h, Wprmu_l, DZ * DH);
    cvt(W_prior_lv, Wprlv_h, Wprlv_l, DZ * DH);
    cvt(W_i2t,      Wi2t_h, Wi2t_l, DT * DIN);
    cvt(W_rec1,     Wr1_h,  Wr1_l,  DREC * DZ);
    cvt(W_rec2,     Wr2_h,  Wr2_l,  DIN * DREC);

    // mu_q = relu(I_t @ W_post_mu^T)
    tc_gemm<1, 64, false><<<g256, blk>>>(It_h, It_l, Wpmu_h, Wpmu_l, DIN,
                                         nullptr, nullptr, nullptr, nullptr, 0,
                                         mu_q, DZ, nullptr, nullptr, nullptr, nullptr);
    // sigma_q = relu(I_t @ W_post_lv^T)
    tc_gemm<1, 64, false><<<g256, blk>>>(It_h, It_l, Wplv_h, Wplv_l, DIN,
                                         nullptr, nullptr, nullptr, nullptr, 0,
                                         sigma_q, DZ, nullptr, nullptr, nullptr, nullptr);
    // ti = I_t @ W_i2t^T
    tc_gemm<0, 16, false><<<g16, blk>>>(It_h, It_l, Wi2t_h, Wi2t_l, DIN,
                                        nullptr, nullptr, nullptr, nullptr, 0,
                                        ti, DT, nullptr, nullptr, nullptr, nullptr);
    // sigma_p = softplus_beta(h_m_1 @ W_prior_lv^T, 1.2)
    tc_gemm<2, 64, false><<<g256, blk>>>(h_h, h_l, Wprlv_h, Wprlv_l, DH,
                                         nullptr, nullptr, nullptr, nullptr, 0,
                                         sigma_p, DZ, nullptr, nullptr, nullptr, nullptr);
    // z_hat = relu(h_m_1 @ W_prior_mu^T) + eps_zhat * sigma_p
    tc_gemm<3, 64, false><<<g256, blk>>>(h_h, h_l, Wprmu_h, Wprmu_l, DH,
                                         nullptr, nullptr, nullptr, nullptr, 0,
                                         out_zhat, DZ, eps_zhat, sigma_p, nullptr, nullptr);
    // h = relu(z_m_1 @ W_z2h^T + h_m_1 @ W_h2h^T)
    tc_gemm<1, 64, true><<<g256, blk>>>(zm_h, zm_l, Wz2h_h, Wz2h_l, DZ,
                                        h_h, h_l, Wh2h_h, Wh2h_l, DH,
                                        out_h, DH, nullptr, nullptr, nullptr, nullptr);
    // theta -> thresholds -> z (+ temporal, energy), emits z bf16 hi/lo
    z_kernel<<<BATCH / 16, blk>>>(theta_m_1, W_vip2t, W_t2z, eps_z, out_zhat, out_z);
    // r1 = z @ W_rec1^T  (emit bf16 hi/lo)
    tc_gemm<5, 64, false><<<g256, blk>>>(z_h, z_l, Wr1_h, Wr1_l, DZ,
                                         nullptr, nullptr, nullptr, nullptr, 0,
                                         nullptr, DREC, nullptr, nullptr, r1_h, r1_l);
    // I_hat = sigmoid(r1 @ W_rec2^T)  (+ spatial loss)
    tc_gemm<4, 64, false><<<g1024, blk>>>(r1_h, r1_l, Wr2_h, Wr2_l, DREC,
                                          nullptr, nullptr, nullptr, nullptr, 0,
                                          out_ihat, DIN, I_t, nullptr, nullptr, nullptr);

    finalize_kernel<<<1, 32>>>(out_scal);
    (void)in_sizes; (void)n_in; (void)out_size;
}

// round 4
// speedup vs baseline: 2.0527x; 1.2257x over previous
#include <cuda_runtime.h>
#include <cuda_bf16.h>
#include <mma.h>
#include <math.h>
#include <stdint.h>

using namespace nvcuda;
typedef __nv_bfloat16 bf16;

#define BATCH 8192
#define DIN   1024
#define DZ    256
#define DH    256
#define DT    16
#define DREC  256

// ---------------- scratch (device globals) ----------------------------------
__device__ float g_mu_q   [BATCH * DZ];
__device__ float g_sigma_q[BATCH * DZ];
__device__ float g_sigma_p[BATCH * DZ];
__device__ float g_mu_p   [BATCH * DZ];
__device__ float g_ti     [BATCH * DT];
__device__ double g_acc[3];

__device__ bf16 g_It_hi [BATCH * DIN], g_It_lo [BATCH * DIN];
__device__ bf16 g_h_hi  [BATCH * DH],  g_h_lo  [BATCH * DH];
__device__ bf16 g_zm_hi [BATCH * DZ],  g_zm_lo [BATCH * DZ];
__device__ bf16 g_z_hi  [BATCH * DZ],  g_z_lo  [BATCH * DZ];
__device__ bf16 g_r1_hi [BATCH * DREC], g_r1_lo[BATCH * DREC];
__device__ bf16 g_Wpmu_hi [DZ * DIN],  g_Wpmu_lo [DZ * DIN];
__device__ bf16 g_Wplv_hi [DZ * DIN],  g_Wplv_lo [DZ * DIN];
__device__ bf16 g_Wz2h_hi [DH * DZ],   g_Wz2h_lo [DH * DZ];
__device__ bf16 g_Wh2h_hi [DH * DH],   g_Wh2h_lo [DH * DH];
__device__ bf16 g_Wprmu_hi[DZ * DH],   g_Wprmu_lo[DZ * DH];
__device__ bf16 g_Wprlv_hi[DZ * DH],   g_Wprlv_lo[DZ * DH];
__device__ bf16 g_Wi2t_hi [64 * DIN],  g_Wi2t_lo [64 * DIN];   // padded 16->64 rows
__device__ bf16 g_Wr1_hi  [DREC * DZ], g_Wr1_lo  [DREC * DZ];
__device__ bf16 g_Wr2_hi  [DIN * DREC], g_Wr2_lo [DIN * DREC];

// ---------------- helpers ----------------------------------------------------
__device__ __forceinline__ float sp_beta(float x, float beta, float invb) {
    float t = beta * x;
    if (t > 20.f) return x;
    return log1pf(expf(t)) * invb;
}

__device__ __forceinline__ uint32_t smem_u32(const void* p) {
    uint32_t a;
    asm("{ .reg .u64 t; cvta.to.shared.u64 t, %1; cvt.u32.u64 %0, t; }" : "=r"(a) : "l"(p));
    return a;
}

__device__ __forceinline__ void cp16(uint32_t dst, const void* src) {
    asm volatile("cp.async.cg.shared.global [%0], [%1], 16;" :: "r"(dst), "l"(src));
}

__device__ __forceinline__ void cvt_store(float4 v, bf16* hi, bf16* lo, size_t e) {
    __nv_bfloat162 h0 = __float22bfloat162_rn(make_float2(v.x, v.y));
    __nv_bfloat162 h1 = __float22bfloat162_rn(make_float2(v.z, v.w));
    float2 f0 = __bfloat1622float2(h0);
    float2 f1 = __bfloat1622float2(h1);
    __nv_bfloat162 l0 = __float22bfloat162_rn(make_float2(v.x - f0.x, v.y - f0.y));
    __nv_bfloat162 l1 = __float22bfloat162_rn(make_float2(v.z - f1.x, v.w - f1.y));
    uint2 hv, lv;
    hv.x = *(uint32_t*)&h0; hv.y = *(uint32_t*)&h1;
    lv.x = *(uint32_t*)&l0; lv.y = *(uint32_t*)&l1;
    *(uint2*)(hi + e) = hv;
    *(uint2*)(lo + e) = lv;
}

// ---------------- batched fp32 -> bf16 hi/lo conversion ----------------------
// Segments in float4 units; one launch covers all operands + Wi2t zero-pad.
#define S_IT    2097152
#define S_H     524288
#define S_ZM    524288
#define S_W256  65536
#define S_W64   16384
#define S_WI2T  4096
#define S_PAD   12288
#define CVT_TOTAL (S_IT + S_H + S_ZM + 2*S_W256 + 4*S_W64 + S_WI2T + S_PAD + S_W64 + S_W256)

__global__ __launch_bounds__(256)
void cvt_all(const float4* __restrict__ It, const float4* __restrict__ h,
             const float4* __restrict__ zm,
             const float4* __restrict__ Wpmu, const float4* __restrict__ Wplv,
             const float4* __restrict__ Wz2h, const float4* __restrict__ Wh2h,
             const float4* __restrict__ Wprmu, const float4* __restrict__ Wprlv,
             const float4* __restrict__ Wi2t, const float4* __restrict__ Wr1,
             const float4* __restrict__ Wr2)
{
    long i = (long)blockIdx.x * 256 + threadIdx.x;
    long o = i;
    if (o < S_IT)   { cvt_store(It[o],   g_It_hi,   g_It_lo,   (size_t)o*4); return; }  o -= S_IT;
    if (o < S_H)    { cvt_store(h[o],    g_h_hi,    g_h_lo,    (size_t)o*4); return; }  o -= S_H;
    if (o < S_ZM)   { cvt_store(zm[o],   g_zm_hi,   g_zm_lo,   (size_t)o*4); return; }  o -= S_ZM;
    if (o < S_W256) { cvt_store(Wpmu[o], g_Wpmu_hi, g_Wpmu_lo, (size_t)o*4); return; }  o -= S_W256;
    if (o < S_W256) { cvt_store(Wplv[o], g_Wplv_hi, g_Wplv_lo, (size_t)o*4); return; }  o -= S_W256;
    if (o < S_W64)  { cvt_store(Wz2h[o], g_Wz2h_hi, g_Wz2h_lo, (size_t)o*4); return; }  o -= S_W64;
    if (o < S_W64)  { cvt_store(Wh2h[o], g_Wh2h_hi, g_Wh2h_lo, (size_t)o*4); return; }  o -= S_W64;
    if (o < S_W64)  { cvt_store(Wprmu[o], g_Wprmu_hi, g_Wprmu_lo, (size_t)o*4); return; } o -= S_W64;
    if (o < S_W64)  { cvt_store(Wprlv[o], g_Wprlv_hi, g_Wprlv_lo, (size_t)o*4); return; } o -= S_W64;
    if (o < S_WI2T) { cvt_store(Wi2t[o], g_Wi2t_hi, g_Wi2t_lo, (size_t)o*4); return; }  o -= S_WI2T;
    if (o < S_PAD)  { // zero pad rows 16..63 of Wi2t
        size_t e = (size_t)(S_WI2T + o) * 4;
        uint2 z = make_uint2(0u, 0u);
        *(uint2*)(g_Wi2t_hi + e) = z;
        *(uint2*)(g_Wi2t_lo + e) = z;
        return;
    }               o -= S_PAD;
    if (o < S_W64)  { cvt_store(Wr1[o],  g_Wr1_hi,  g_Wr1_lo,  (size_t)o*4); return; }  o -= S_W64;
    if (o < S_W256) { cvt_store(Wr2[o],  g_Wr2_hi,  g_Wr2_lo,  (size_t)o*4); }
}

// ============================================================================
// WMMA bf16 hi/lo GEMM, cp.async 2-stage double buffered.
// BM=128, BN=64, BK=32, 256 threads (8 warps, 4x2 warp grid, 32x32 warp tile).
// MODE 0: A=I_t (K=1024): bx<4 mu_q relu; bx<8 sigma_q relu; bx==8 ti store
// MODE 1: A=h_m_1 (K=256): bx<4 mu_p relu; bx>=4 sigma_p softplus(1.2)
// MODE 2: dual-source relu (h update)
// MODE 3: bf16 hi/lo emit (r1)
// MODE 4: sigmoid + spatial loss (rec2, N=1024)
// ============================================================================
#define STAGE_BYTES 30720
#define SMEM_TOTAL_BYTES 61440   // 2 stages; epilogue sC (32KB) reuses stage 0+

template<int MODE>
__global__ __launch_bounds__(256)
void tc_gemm(const bf16* __restrict__ A0h, const bf16* __restrict__ A0l, int K0,
             const bf16* __restrict__ A1h, const bf16* __restrict__ A1l, int K1,
             const bf16* __restrict__ B0h, const bf16* __restrict__ B0l,
             const bf16* __restrict__ B1h, const bf16* __restrict__ B1l,
             const bf16* __restrict__ B2h, const bf16* __restrict__ B2l,
             float* __restrict__ C0, float* __restrict__ C1, float* __restrict__ C2,
             const float* __restrict__ aux0,
             bf16* __restrict__ Chi, bf16* __restrict__ Clo)
{
    constexpr int P = 40;   // smem pitch in bf16 (80B, 16B-aligned, conflict-free)
    extern __shared__ __align__(16) char smem[];
    __shared__ float red[256];

    const int tid = threadIdx.x;
    const int wid = tid >> 5;
    const int bx = blockIdx.x, by = blockIdx.y;
    const int wm = wid >> 1, wn = wid & 1;

    // ---- per-CTA B selection ----
    const bf16 *Bh, *Bl;
    int brow0;
    if (MODE == 0) {
        int wsel = bx >> 2;
        Bh = (wsel == 0) ? B0h : (wsel == 1) ? B1h : B2h;
        Bl = (wsel == 0) ? B0l : (wsel == 1) ? B1l : B2l;
        brow0 = (bx & 3) * 64;
    } else if (MODE == 1) {
        Bh = (bx < 4) ? B0h : B1h;
        Bl = (bx < 4) ? B0l : B1l;
        brow0 = (bx & 3) * 64;
    } else {
        Bh = B0h; Bl = B0l;
        brow0 = bx * 64;
    }

    const int nc0 = K0 / 32;
    const int nc = (MODE == 2) ? (K0 + K1) / 32 : nc0;

    const uint32_t smb = smem_u32(smem);

    auto issue = [&](int c, int s) {
        const bf16 *Ah, *Al, *Bh_, *Bl_;
        int K, kc;
        if (MODE == 2 && c >= nc0) {
            Ah = A1h; Al = A1l; Bh_ = B1h; Bl_ = B1l; K = K1; kc = (c - nc0) * 32;
        } else {
            Ah = A0h; Al = A0l; Bh_ = Bh; Bl_ = Bl;
            K = K0; kc = c * 32;
        }
        uint32_t sA = smb + s * STAGE_BYTES;
#pragma unroll
        for (int it = 0; it < 2; ++it) {
            int i = tid + it * 256;
            int row = i >> 2, kq = i & 3;
            size_t g = (size_t)(by * 128 + row) * K + kc + kq * 8;
            cp16(sA + row * 80 + kq * 16, Ah + g);
            cp16(sA + 10240 + row * 80 + kq * 16, Al + g);
        }
        {
            int row = tid >> 2, kq = tid & 3;
            size_t g = (size_t)(brow0 + row) * K + kc + kq * 8;
            cp16(sA + 20480 + row * 80 + kq * 16, Bh_ + g);
            cp16(sA + 25600 + row * 80 + kq * 16, Bl_ + g);
        }
        asm volatile("cp.async.commit_group;" ::: "memory");
    };

    wmma::fragment<wmma::accumulator, 16, 16, 16, float> acc[2][2];
#pragma unroll
    for (int tm = 0; tm < 2; ++tm)
#pragma unroll
        for (int tn = 0; tn < 2; ++tn)
            wmma::fill_fragment(acc[tm][tn], 0.f);

    issue(0, 0);

    for (int c = 0; c < nc; ++c) {
        asm volatile("cp.async.wait_group 0;" ::: "memory");
        __syncthreads();
        if (c + 1 < nc) issue(c + 1, (c + 1) & 1);

        const bf16* sAh = (const bf16*)(smem + (c & 1) * STAGE_BYTES);
        const bf16* sAl = sAh + 128 * P;
        const bf16* sBh = sAl + 128 * P;
        const bf16* sBl = sBh + 64 * P;

#pragma unroll
        for (int ks = 0; ks < 2; ++ks) {
            wmma::fragment<wmma::matrix_a, 16, 16, 16, bf16, wmma::row_major> ah[2], al[2];
            wmma::fragment<wmma::matrix_b, 16, 16, 16, bf16, wmma::col_major> bh[2], bl[2];
#pragma unroll
            for (int tm = 0; tm < 2; ++tm) {
                const bf16* p = sAh + (wm * 32 + tm * 16) * P + ks * 16;
                wmma::load_matrix_sync(ah[tm], p, P);
                wmma::load_matrix_sync(al[tm], p + 128 * P, P);
            }
#pragma unroll
            for (int tn = 0; tn < 2; ++tn) {
                const bf16* p = sBh + (wn * 32 + tn * 16) * P + ks * 16;
                wmma::load_matrix_sync(bh[tn], p, P);
                wmma::load_matrix_sync(bl[tn], p + 64 * P, P);
            }
            // term-outer ordering: 4 independent acc chains between reuses
#pragma unroll
            for (int tm = 0; tm < 2; ++tm)
#pragma unroll
                for (int tn = 0; tn < 2; ++tn)
                    wmma::mma_sync(acc[tm][tn], ah[tm], bh[tn], acc[tm][tn]);
#pragma unroll
            for (int tm = 0; tm < 2; ++tm)
#pragma unroll
                for (int tn = 0; tn < 2; ++tn)
                    wmma::mma_sync(acc[tm][tn], ah[tm], bl[tn], acc[tm][tn]);
#pragma unroll
            for (int tm = 0; tm < 2; ++tm)
#pragma unroll
                for (int tn = 0; tn < 2; ++tn)
                    wmma::mma_sync(acc[tm][tn], al[tm], bh[tn], acc[tm][tn]);
        }
    }

    // ---- stage to smem ----
    __syncthreads();
    float* sC = (float*)smem;
#pragma unroll
    for (int tm = 0; tm < 2; ++tm)
#pragma unroll
        for (int tn = 0; tn < 2; ++tn)
            wmma::store_matrix_sync(sC + (wm * 32 + tm * 16) * 64 + wn * 32 + tn * 16,
                                    acc[tm][tn], 64, wmma::mem_row_major);
    __syncthreads();

    // ---- epilogue ----
    if (MODE == 0 && bx == 8) {   // ti: [B,16]
        int row = tid >> 1, c0 = (tid & 1) * 8;
        size_t gb = (size_t)(by * 128 + row) * DT + c0;
        *(float4*)(C2 + gb)     = *(const float4*)(sC + row * 64 + c0);
        *(float4*)(C2 + gb + 4) = *(const float4*)(sC + row * 64 + c0 + 4);
        return;
    }

    float lsum = 0.f;
    const int tx = tid & 15, ty = tid >> 4;
    const int N = (MODE == 4) ? 1024 : 256;
    int col0;
    float* Cd = C0;
    if (MODE == 0)      { Cd = (bx < 4) ? C0 : C1; col0 = (bx & 3) * 64; }
    else if (MODE == 1) { Cd = (bx < 4) ? C0 : C1; col0 = (bx & 3) * 64; }
    else                {                          col0 = bx * 64; }
    const bool do_softplus = (MODE == 1) && (bx >= 4);

#pragma unroll
    for (int i = 0; i < 8; ++i) {
        int row = ty * 8 + i;
        size_t gbase = (size_t)(by * 128 + row) * N + col0 + tx * 4;
        float4 v = *(const float4*)(sC + row * 64 + tx * 4);
        float* vp = &v.x;
        float4 a0;
        if (MODE == 4) a0 = *(const float4*)(aux0 + gbase);
        const float* a0p = &a0.x;
        float4 o; float* op = &o.x;
#pragma unroll
        for (int jj = 0; jj < 4; ++jj) {
            float a = vp[jj];
            float ov;
            if (MODE == 0 || MODE == 2)      ov = fmaxf(a, 0.f);
            else if (MODE == 1) ov = do_softplus ? sp_beta(a, 1.2f, 1.f / 1.2f)
                                                 : fmaxf(a, 0.f);
            else if (MODE == 4) { ov = 1.f / (1.f + expf(-a)); float dd = a0p[jj] - ov; lsum += dd * dd; }
            else                ov = a;   // MODE 3
            op[jj] = ov;
        }
        if (MODE == 3) {
            __nv_bfloat162 h0 = __float22bfloat162_rn(make_float2(o.x, o.y));
            __nv_bfloat162 h1 = __float22bfloat162_rn(make_float2(o.z, o.w));
            float2 f0 = __bfloat1622float2(h0);
            float2 f1 = __bfloat1622float2(h1);
            __nv_bfloat162 l0 = __float22bfloat162_rn(make_float2(o.x - f0.x, o.y - f0.y));
            __nv_bfloat162 l1 = __float22bfloat162_rn(make_float2(o.z - f1.x, o.w - f1.y));
            *(uint32_t*)(Chi + gbase)     = *(uint32_t*)&h0;
            *(uint32_t*)(Chi + gbase + 2) = *(uint32_t*)&h1;
            *(uint32_t*)(Clo + gbase)     = *(uint32_t*)&l0;
            *(uint32_t*)(Clo + gbase + 2) = *(uint32_t*)&l1;
        } else {
            *(float4*)(Cd + gbase) = o;
        }
    }

    if (MODE == 4) {
        red[tid] = lsum;
        __syncthreads();
#pragma unroll
        for (int s = 128; s > 0; s >>= 1) {
            if (tid < s) red[tid] += red[tid + s];
            __syncthreads();
        }
        if (tid == 0) atomicAdd(&g_acc[0], (double)red[0]);
    }
}

// ---------------- fused theta/threshold/z + z_hat + losses ------------------
__global__ __launch_bounds__(256)
void z_kernel(const float* __restrict__ theta_m_1,
              const float* __restrict__ W_vip2t,
              const float* __restrict__ W_t2z,
              const float* __restrict__ eps_z,
              const float* __restrict__ eps_zhat,
              float* __restrict__ z_out,
              float* __restrict__ zhat_out)
{
    const int R = 16;
    __shared__ float sWv[DT][DZ + 1];
    __shared__ float sSp[R][DZ + 1];
    __shared__ float sTheta[R][DT + 1];
    __shared__ float red[256];

    const int tid = threadIdx.x;
    const int row0 = blockIdx.x * R;

    for (int idx = tid; idx < DT * DZ; idx += 256) {
        int t = idx >> 8, n = idx & 255;
        sWv[t][n] = fmaxf(W_vip2t[idx], 0.f);
    }
    for (int idx = tid; idx < R * DZ; idx += 256) {
        int r = idx >> 8, n = idx & 255;
        sSp[r][n] = g_sigma_p[(size_t)(row0 + r) * DZ + n];
    }
    __syncthreads();

    {
        int r = tid >> 4, t = tid & 15;
        float dot = 0.f;
#pragma unroll 8
        for (int n = 0; n < DZ; n++)
            dot = fmaf(sSp[r][n], sWv[t][n], dot);
        size_t tix = (size_t)(row0 + r) * DT + t;
        float th_h = 0.5f * theta_m_1[tix] + 0.1f * g_ti[tix] - dot;
        float u = 0.5f * th_h;
        float sp = (u > 20.f) ? th_h : log1pf(expf(u)) * 2.0f;
        sTheta[r][t] = 0.001f * sp;
    }
    __syncthreads();

    const int n = tid;
    float wt[DT];
#pragma unroll
    for (int t = 0; t < DT; t++)
        wt[t] = fmaxf(W_t2z[(size_t)n * DT + t], 0.f);

    float e_sum = 0.f, t_sum = 0.f;
    for (int r = 0; r < R; r++) {
        float thr = 0.f;
#pragma unroll
        for (int t = 0; t < DT; t++)
            thr = fmaf(sTheta[r][t], wt[t], thr);
        thr *= 10.f;
        size_t idx = (size_t)(row0 + r) * DZ + n;
        float raw = fmaf(eps_z[idx], g_sigma_q[idx], g_mu_q[idx]);
        raw = fminf(fmaxf(raw, 0.f), 1.f);
        float zv = fmaxf(raw - thr, 0.f);
        z_out[idx] = zv;
        bf16 h = __float2bfloat16_rn(zv);
        g_z_hi[idx] = h;
        g_z_lo[idx] = __float2bfloat16_rn(zv - __bfloat162float(h));
        // z_hat = relu(mu_p) + eps_zhat * sigma_p   (mu_p already relu'd)
        float zh = fmaf(eps_zhat[idx], sSp[r][n], g_mu_p[idx]);
        zhat_out[idx] = zh;
        e_sum += zv;
        float d = zv - zh;
        t_sum = fmaf(d, d, t_sum);
    }

    red[tid] = e_sum; __syncthreads();
#pragma unroll
    for (int s = 128; s > 0; s >>= 1) { if (tid < s) red[tid] += red[tid + s]; __syncthreads(); }
    if (tid == 0) atomicAdd(&g_acc[2], (double)red[0]);
    __syncthreads();
    red[tid] = t_sum; __syncthreads();
#pragma unroll
    for (int s = 128; s > 0; s >>= 1) { if (tid < s) red[tid] += red[tid + s]; __syncthreads(); }
    if (tid == 0) atomicAdd(&g_acc[1], (double)red[0]);
}

// ---------------- scalar setup / finalize -----------------------------------
__global__ void zero_acc_kernel() {
    if (threadIdx.x < 3) g_acc[threadIdx.x] = 0.0;
}

__global__ void finalize_kernel(float* __restrict__ out_scalars) {
    if (threadIdx.x == 0) {
        out_scalars[0] = (float)(g_acc[0] / (double)((size_t)BATCH * DIN));
        out_scalars[1] = (float)(g_acc[1] / (double)((size_t)BATCH * DZ));
        out_scalars[2] = (float)(g_acc[2] / (double)((size_t)BATCH * DZ));
    }
}

// ---------------- launch -----------------------------------------------------
extern "C" void kernel_launch(void* const* d_in, const int* in_sizes, int n_in,
                              void* d_out, int out_size)
{
    const float* I_t        = (const float*)d_in[0];
    const float* h_m_1      = (const float*)d_in[1];
    const float* z_m_1      = (const float*)d_in[2];
    const float* theta_m_1  = (const float*)d_in[3];
    const float* eps_z      = (const float*)d_in[4];
    const float* eps_zhat   = (const float*)d_in[5];
    const float* W_post_mu  = (const float*)d_in[6];
    const float* W_post_lv  = (const float*)d_in[7];
    const float* W_z2h      = (const float*)d_in[8];
    const float* W_h2h      = (const float*)d_in[9];
    const float* W_prior_mu = (const float*)d_in[10];
    const float* W_prior_lv = (const float*)d_in[11];
    const float* W_i2t      = (const float*)d_in[12];
    const float* W_vip2t    = (const float*)d_in[13];
    const float* W_t2z      = (const float*)d_in[14];
    const float* W_rec1     = (const float*)d_in[15];
    const float* W_rec2     = (const float*)d_in[16];

    float* out       = (float*)d_out;
    float* out_ihat  = out;
    float* out_z     = out + (size_t)BATCH * DIN;
    float* out_h     = out_z + (size_t)BATCH * DZ;
    float* out_zhat  = out_h + (size_t)BATCH * DH;
    float* out_scal  = out_zhat + (size_t)BATCH * DZ;

    float *mu_q, *sigma_q, *sigma_p, *mu_p, *ti;
    cudaGetSymbolAddress((void**)&mu_q,    g_mu_q);
    cudaGetSymbolAddress((void**)&sigma_q, g_sigma_q);
    cudaGetSymbolAddress((void**)&sigma_p, g_sigma_p);
    cudaGetSymbolAddress((void**)&mu_p,    g_mu_p);
    cudaGetSymbolAddress((void**)&ti,      g_ti);
    bf16 *It_h, *It_l, *h_h, *h_l, *zm_h, *zm_l, *z_h, *z_l, *r1_h, *r1_l;
    bf16 *Wpmu_h, *Wpmu_l, *Wplv_h, *Wplv_l, *Wz2h_h, *Wz2h_l, *Wh2h_h, *Wh2h_l;
    bf16 *Wprmu_h, *Wprmu_l, *Wprlv_h, *Wprlv_l, *Wi2t_h, *Wi2t_l;
    bf16 *Wr1_h, *Wr1_l, *Wr2_h, *Wr2_l;
    cudaGetSymbolAddress((void**)&It_h, g_It_hi);   cudaGetSymbolAddress((void**)&It_l, g_It_lo);
    cudaGetSymbolAddress((void**)&h_h,  g_h_hi);    cudaGetSymbolAddress((void**)&h_l,  g_h_lo);
    cudaGetSymbolAddress((void**)&zm_h, g_zm_hi);   cudaGetSymbolAddress((void**)&zm_l, g_zm_lo);
    cudaGetSymbolAddress((void**)&z_h,  g_z_hi);    cudaGetSymbolAddress((void**)&z_l,  g_z_lo);
    cudaGetSymbolAddress((void**)&r1_h, g_r1_hi);   cudaGetSymbolAddress((void**)&r1_l, g_r1_lo);
    cudaGetSymbolAddress((void**)&Wpmu_h, g_Wpmu_hi);   cudaGetSymbolAddress((void**)&Wpmu_l, g_Wpmu_lo);
    cudaGetSymbolAddress((void**)&Wplv_h, g_Wplv_hi);   cudaGetSymbolAddress((void**)&Wplv_l, g_Wplv_lo);
    cudaGetSymbolAddress((void**)&Wz2h_h, g_Wz2h_hi);   cudaGetSymbolAddress((void**)&Wz2h_l, g_Wz2h_lo);
    cudaGetSymbolAddress((void**)&Wh2h_h, g_Wh2h_hi);   cudaGetSymbolAddress((void**)&Wh2h_l, g_Wh2h_lo);
    cudaGetSymbolAddress((void**)&Wprmu_h, g_Wprmu_hi); cudaGetSymbolAddress((void**)&Wprmu_l, g_Wprmu_lo);
    cudaGetSymbolAddress((void**)&Wprlv_h, g_Wprlv_hi); cudaGetSymbolAddress((void**)&Wprlv_l, g_Wprlv_lo);
    cudaGetSymbolAddress((void**)&Wi2t_h, g_Wi2t_hi);   cudaGetSymbolAddress((void**)&Wi2t_l, g_Wi2t_lo);
    cudaGetSymbolAddress((void**)&Wr1_h, g_Wr1_hi);     cudaGetSymbolAddress((void**)&Wr1_l, g_Wr1_lo);
    cudaGetSymbolAddress((void**)&Wr2_h, g_Wr2_hi);     cudaGetSymbolAddress((void**)&Wr2_l, g_Wr2_lo);

    cudaFuncSetAttribute(tc_gemm<0>, cudaFuncAttributeMaxDynamicSharedMemorySize, SMEM_TOTAL_BYTES);
    cudaFuncSetAttribute(tc_gemm<1>, cudaFuncAttributeMaxDynamicSharedMemorySize, SMEM_TOTAL_BYTES);
    cudaFuncSetAttribute(tc_gemm<2>, cudaFuncAttributeMaxDynamicSharedMemorySize, SMEM_TOTAL_BYTES);
    cudaFuncSetAttribute(tc_gemm<3>, cudaFuncAttributeMaxDynamicSharedMemorySize, SMEM_TOTAL_BYTES);
    cudaFuncSetAttribute(tc_gemm<4>, cudaFuncAttributeMaxDynamicSharedMemorySize, SMEM_TOTAL_BYTES);

    const dim3 blk(256);
    zero_acc_kernel<<<1, 32>>>();

    cvt_all<<<(CVT_TOTAL + 255) / 256, blk>>>(
        (const float4*)I_t, (const float4*)h_m_1, (const float4*)z_m_1,
        (const float4*)W_post_mu, (const float4*)W_post_lv,
        (const float4*)W_z2h, (const float4*)W_h2h,
        (const float4*)W_prior_mu, (const float4*)W_prior_lv,
        (const float4*)W_i2t, (const float4*)W_rec1, (const float4*)W_rec2);

    // MODE0: mu_q, sigma_q, ti (one pass over I_t)
    tc_gemm<0><<<dim3(9, BATCH / 128), blk, SMEM_TOTAL_BYTES>>>(
        It_h, It_l, DIN, nullptr, nullptr, 0,
        Wpmu_h, Wpmu_l, Wplv_h, Wplv_l, Wi2t_h, Wi2t_l,
        mu_q, sigma_q, ti, nullptr, nullptr, nullptr);

    // MODE1: mu_p (relu), sigma_p (softplus)
    tc_gemm<1><<<dim3(8, BATCH / 128), blk, SMEM_TOTAL_BYTES>>>(
        h_h, h_l, DH, nullptr, nullptr, 0,
        Wprmu_h, Wprmu_l, Wprlv_h, Wprlv_l, nullptr, nullptr,
        mu_p, sigma_p, nullptr, nullptr, nullptr, nullptr);

    // MODE2: h = relu(z_m_1 @ W_z2h^T + h_m_1 @ W_h2h^T)
    tc_gemm<2><<<dim3(4, BATCH / 128), blk, SMEM_TOTAL_BYTES>>>(
        zm_h, zm_l, DZ, h_h, h_l, DH,
        Wz2h_h, Wz2h_l, Wh2h_h, Wh2h_l, nullptr, nullptr,
        out_h, nullptr, nullptr, nullptr, nullptr, nullptr);

    // z, z_hat, energy, temporal
    z_kernel<<<BATCH / 16, blk>>>(theta_m_1, W_vip2t, W_t2z, eps_z, eps_zhat,
                                  out_z, out_zhat);

    // MODE3: r1 = z @ W_rec1^T (bf16 hi/lo emit)
    tc_gemm<3><<<dim3(4, BATCH / 128), blk, SMEM_TOTAL_BYTES>>>(
        z_h, z_l, DZ, nullptr, nullptr, 0,
        Wr1_h, Wr1_l, nullptr, nullptr, nullptr, nullptr,
        nullptr, nullptr, nullptr, nullptr, r1_h, r1_l);

    // MODE4: I_hat = sigmoid(r1 @ W_rec2^T) + spatial loss
    tc_gemm<4><<<dim3(16, BATCH / 128), blk, SMEM_TOTAL_BYTES>>>(
        r1_h, r1_l, DREC, nullptr, nullptr, 0,
        Wr2_h, Wr2_l, nullptr, nullptr, nullptr, nullptr,
        out_ihat, nullptr, nullptr, I_t, nullptr, nullptr);

    finalize_kernel<<<1, 32>>>(out_scal);
    (void)in_sizes; (void)n_in; (void)out_size;
}

// round 5
// speedup vs baseline: 2.1002x; 1.0231x over previous
#include <cuda_runtime.h>
#include <cuda_bf16.h>
#include <mma.h>
#include <math.h>
#include <stdint.h>

using namespace nvcuda;
typedef __nv_bfloat16 bf16;

#define BATCH 8192
#define DIN   1024
#define DZ    256
#define DH    256
#define DT    16
#define DREC  256

// ---------------- scratch (device globals) ----------------------------------
__device__ float g_mu_q   [BATCH * DZ];
__device__ float g_sigma_q[BATCH * DZ];
__device__ float g_sigma_p[BATCH * DZ];
__device__ float g_mu_p   [BATCH * DZ];
__device__ float g_ti     [BATCH * DT];
__device__ double g_acc[3];

__device__ bf16 g_It_hi [BATCH * DIN], g_It_lo [BATCH * DIN];
__device__ bf16 g_h_hi  [BATCH * DH],  g_h_lo  [BATCH * DH];
__device__ bf16 g_zm_hi [BATCH * DZ],  g_zm_lo [BATCH * DZ];
__device__ bf16 g_z_hi  [BATCH * DZ],  g_z_lo  [BATCH * DZ];
__device__ bf16 g_r1_hi [BATCH * DREC], g_r1_lo[BATCH * DREC];
__device__ bf16 g_Wpmu_hi [DZ * DIN],  g_Wpmu_lo [DZ * DIN];
__device__ bf16 g_Wplv_hi [DZ * DIN],  g_Wplv_lo [DZ * DIN];
__device__ bf16 g_Wz2h_hi [DH * DZ],   g_Wz2h_lo [DH * DZ];
__device__ bf16 g_Wh2h_hi [DH * DH],   g_Wh2h_lo [DH * DH];
__device__ bf16 g_Wprmu_hi[DZ * DH],   g_Wprmu_lo[DZ * DH];
__device__ bf16 g_Wprlv_hi[DZ * DH],   g_Wprlv_lo[DZ * DH];
__device__ bf16 g_Wi2t_hi [64 * DIN],  g_Wi2t_lo [64 * DIN];   // padded 16->64
__device__ bf16 g_Wr1_hi  [DREC * DZ], g_Wr1_lo  [DREC * DZ];
__device__ bf16 g_Wr2_hi  [DIN * DREC], g_Wr2_lo [DIN * DREC];

// ---------------- helpers ----------------------------------------------------
__device__ __forceinline__ float sp_beta(float x, float beta, float invb) {
    float t = beta * x;
    if (t > 20.f) return x;
    return log1pf(expf(t)) * invb;
}

__device__ __forceinline__ uint32_t smem_u32(const void* p) {
    uint32_t a;
    asm("{ .reg .u64 t; cvta.to.shared.u64 t, %1; cvt.u32.u64 %0, t; }" : "=r"(a) : "l"(p));
    return a;
}

__device__ __forceinline__ void cp16(uint32_t dst, const void* src) {
    asm volatile("cp.async.cg.shared.global [%0], [%1], 16;" :: "r"(dst), "l"(src));
}

__device__ __forceinline__ void cvt_store(float4 v, bf16* hi, bf16* lo, size_t e) {
    __nv_bfloat162 h0 = __float22bfloat162_rn(make_float2(v.x, v.y));
    __nv_bfloat162 h1 = __float22bfloat162_rn(make_float2(v.z, v.w));
    float2 f0 = __bfloat1622float2(h0);
    float2 f1 = __bfloat1622float2(h1);
    __nv_bfloat162 l0 = __float22bfloat162_rn(make_float2(v.x - f0.x, v.y - f0.y));
    __nv_bfloat162 l1 = __float22bfloat162_rn(make_float2(v.z - f1.x, v.w - f1.y));
    uint2 hv, lv;
    hv.x = *(uint32_t*)&h0; hv.y = *(uint32_t*)&h1;
    lv.x = *(uint32_t*)&l0; lv.y = *(uint32_t*)&l1;
    *(uint2*)(hi + e) = hv;
    *(uint2*)(lo + e) = lv;
}

// ---------------- batched fp32 -> bf16 hi/lo conversion ----------------------
#define S_IT    2097152
#define S_H     524288
#define S_ZM    524288
#define S_W256  65536
#define S_W64   16384
#define S_WI2T  4096
#define S_PAD   12288
#define CVT_TOTAL (S_IT + S_H + S_ZM + 2*S_W256 + 4*S_W64 + S_WI2T + S_PAD + S_W64 + S_W256)

__device__ __forceinline__ void cvt_one(long o,
    const float4* It, const float4* h, const float4* zm,
    const float4* Wpmu, const float4* Wplv, const float4* Wz2h, const float4* Wh2h,
    const float4* Wprmu, const float4* Wprlv, const float4* Wi2t,
    const float4* Wr1, const float4* Wr2)
{
    if (o < S_IT)   { cvt_store(It[o],   g_It_hi,   g_It_lo,   (size_t)o*4); return; }  o -= S_IT;
    if (o < S_H)    { cvt_store(h[o],    g_h_hi,    g_h_lo,    (size_t)o*4); return; }  o -= S_H;
    if (o < S_ZM)   { cvt_store(zm[o],   g_zm_hi,   g_zm_lo,   (size_t)o*4); return; }  o -= S_ZM;
    if (o < S_W256) { cvt_store(Wpmu[o], g_Wpmu_hi, g_Wpmu_lo, (size_t)o*4); return; }  o -= S_W256;
    if (o < S_W256) { cvt_store(Wplv[o], g_Wplv_hi, g_Wplv_lo, (size_t)o*4); return; }  o -= S_W256;
    if (o < S_W64)  { cvt_store(Wz2h[o], g_Wz2h_hi, g_Wz2h_lo, (size_t)o*4); return; }  o -= S_W64;
    if (o < S_W64)  { cvt_store(Wh2h[o], g_Wh2h_hi, g_Wh2h_lo, (size_t)o*4); return; }  o -= S_W64;
    if (o < S_W64)  { cvt_store(Wprmu[o], g_Wprmu_hi, g_Wprmu_lo, (size_t)o*4); return; } o -= S_W64;
    if (o < S_W64)  { cvt_store(Wprlv[o], g_Wprlv_hi, g_Wprlv_lo, (size_t)o*4); return; } o -= S_W64;
    if (o < S_WI2T) { cvt_store(Wi2t[o], g_Wi2t_hi, g_Wi2t_lo, (size_t)o*4); return; }  o -= S_WI2T;
    if (o < S_PAD)  {
        size_t e = (size_t)(S_WI2T + o) * 4;
        uint2 z = make_uint2(0u, 0u);
        *(uint2*)(g_Wi2t_hi + e) = z;
        *(uint2*)(g_Wi2t_lo + e) = z;
        return;
    }               o -= S_PAD;
    if (o < S_W64)  { cvt_store(Wr1[o],  g_Wr1_hi,  g_Wr1_lo,  (size_t)o*4); return; }  o -= S_W64;
    if (o < S_W256) { cvt_store(Wr2[o],  g_Wr2_hi,  g_Wr2_lo,  (size_t)o*4); }
}

__global__ __launch_bounds__(256)
void cvt_all(const float4* __restrict__ It, const float4* __restrict__ h,
             const float4* __restrict__ zm,
             const float4* __restrict__ Wpmu, const float4* __restrict__ Wplv,
             const float4* __restrict__ Wz2h, const float4* __restrict__ Wh2h,
             const float4* __restrict__ Wprmu, const float4* __restrict__ Wprlv,
             const float4* __restrict__ Wi2t, const float4* __restrict__ Wr1,
             const float4* __restrict__ Wr2)
{
    const long stride = (long)gridDim.x * 256;
    long i = (long)blockIdx.x * 256 + threadIdx.x;
#pragma unroll
    for (int u = 0; u < 4; ++u, i += stride)
        if (i < CVT_TOTAL)
            cvt_one(i, It, h, zm, Wpmu, Wplv, Wz2h, Wh2h, Wprmu, Wprlv, Wi2t, Wr1, Wr2);
}

// ============================================================================
// Shared GEMM machinery: BM=128, BN=64, BK=32, 256 threads, hi/lo 3-term.
// ============================================================================
#define P_PITCH 40
#define STAGE_BYTES 30720
#define SMEM_TOTAL_BYTES 61440

#define GEMM_COMPUTE_CHUNK(sAh_, sAl_, sBh_, sBl_)                                        \
    _Pragma("unroll")                                                                      \
    for (int ks = 0; ks < 2; ++ks) {                                                       \
        wmma::fragment<wmma::matrix_a, 16, 16, 16, bf16, wmma::row_major> fa[2];           \
        wmma::fragment<wmma::matrix_b, 16, 16, 16, bf16, wmma::col_major> fb[2];           \
        _Pragma("unroll")                                                                  \
        for (int tm = 0; tm < 2; ++tm)                                                     \
            wmma::load_matrix_sync(fa[tm], sAh_ + (wm * 32 + tm * 16) * P_PITCH + ks * 16, P_PITCH); \
        _Pragma("unroll")                                                                  \
        for (int tn = 0; tn < 2; ++tn)                                                     \
            wmma::load_matrix_sync(fb[tn], sBh_ + (wn * 32 + tn * 16) * P_PITCH + ks * 16, P_PITCH); \
        _Pragma("unroll")                                                                  \
        for (int tm = 0; tm < 2; ++tm)                                                     \
            _Pragma("unroll")                                                              \
            for (int tn = 0; tn < 2; ++tn)                                                 \
                wmma::mma_sync(acc[tm][tn], fa[tm], fb[tn], acc[tm][tn]);                  \
        {                                                                                  \
            wmma::fragment<wmma::matrix_b, 16, 16, 16, bf16, wmma::col_major> fbl[2];      \
            _Pragma("unroll")                                                              \
            for (int tn = 0; tn < 2; ++tn)                                                 \
                wmma::load_matrix_sync(fbl[tn], sBl_ + (wn * 32 + tn * 16) * P_PITCH + ks * 16, P_PITCH); \
            _Pragma("unroll")                                                              \
            for (int tm = 0; tm < 2; ++tm)                                                 \
                _Pragma("unroll")                                                          \
                for (int tn = 0; tn < 2; ++tn)                                             \
                    wmma::mma_sync(acc[tm][tn], fa[tm], fbl[tn], acc[tm][tn]);             \
        }                                                                                  \
        {                                                                                  \
            wmma::fragment<wmma::matrix_a, 16, 16, 16, bf16, wmma::row_major> fal[2];      \
            _Pragma("unroll")                                                              \
            for (int tm = 0; tm < 2; ++tm)                                                 \
                wmma::load_matrix_sync(fal[tm], sAl_ + (wm * 32 + tm * 16) * P_PITCH + ks * 16, P_PITCH); \
            _Pragma("unroll")                                                              \
            for (int tm = 0; tm < 2; ++tm)                                                 \
                _Pragma("unroll")                                                          \
                for (int tn = 0; tn < 2; ++tn)                                             \
                    wmma::mma_sync(acc[tm][tn], fal[tm], fb[tn], acc[tm][tn]);             \
        }                                                                                  \
    }

// ---------------- front mega-GEMM: mu_q/sigma_q/ti + mu_p/sigma_p + h -------
// bx 0-3 mu_q | 4-7 sigma_q | 8 ti | 9-12 mu_p | 13-16 sigma_p | 17-20 h(dual)
__global__ __launch_bounds__(256, 3)
void gemm_front(const bf16* __restrict__ It_h, const bf16* __restrict__ It_l,
                const bf16* __restrict__ hm_h, const bf16* __restrict__ hm_l,
                const bf16* __restrict__ zm_h, const bf16* __restrict__ zm_l,
                const bf16* __restrict__ Wpmu_h, const bf16* __restrict__ Wpmu_l,
                const bf16* __restrict__ Wplv_h, const bf16* __restrict__ Wplv_l,
                const bf16* __restrict__ Wi2t_h, const bf16* __restrict__ Wi2t_l,
                const bf16* __restrict__ Wprmu_h, const bf16* __restrict__ Wprmu_l,
                const bf16* __restrict__ Wprlv_h, const bf16* __restrict__ Wprlv_l,
                const bf16* __restrict__ Wz2h_h, const bf16* __restrict__ Wz2h_l,
                const bf16* __restrict__ Wh2h_h, const bf16* __restrict__ Wh2h_l,
                float* __restrict__ C_muq, float* __restrict__ C_sigq,
                float* __restrict__ C_ti,  float* __restrict__ C_mup,
                float* __restrict__ C_sigp, float* __restrict__ C_h)
{
    extern __shared__ __align__(16) char smem[];
    const int tid = threadIdx.x;
    const int wid = tid >> 5;
    const int bx = blockIdx.x, by = blockIdx.y;
    const int wm = wid >> 1, wn = wid & 1;

    // route setup
    int route;
    if (bx < 4) route = 0; else if (bx < 8) route = 1; else if (bx == 8) route = 2;
    else if (bx < 13) route = 3; else if (bx < 17) route = 4; else route = 5;

    const bf16 *Ah, *Al, *Bh, *Bl;
    int K, brow0;
    switch (route) {
        case 0: Ah = It_h; Al = It_l; Bh = Wpmu_h; Bl = Wpmu_l; K = DIN; brow0 = (bx & 3) * 64; break;
        case 1: Ah = It_h; Al = It_l; Bh = Wplv_h; Bl = Wplv_l; K = DIN; brow0 = (bx & 3) * 64; break;
        case 2: Ah = It_h; Al = It_l; Bh = Wi2t_h; Bl = Wi2t_l; K = DIN; brow0 = 0; break;
        case 3: Ah = hm_h; Al = hm_l; Bh = Wprmu_h; Bl = Wprmu_l; K = DH; brow0 = (bx - 9) * 64; break;
        case 4: Ah = hm_h; Al = hm_l; Bh = Wprlv_h; Bl = Wprlv_l; K = DH; brow0 = (bx - 13) * 64; break;
        default: Ah = zm_h; Al = zm_l; Bh = Wz2h_h; Bl = Wz2h_l; K = DZ; brow0 = (bx - 17) * 64; break;
    }
    const int nc0 = K / 32;
    const int nc = (route == 5) ? nc0 + DH / 32 : nc0;

    const uint32_t smb = smem_u32(smem);

    auto issue = [&](int c, int s) {
        const bf16 *Ah_, *Al_, *Bh_, *Bl_;
        int K_, kc;
        if (route == 5 && c >= nc0) {
            Ah_ = hm_h; Al_ = hm_l; Bh_ = Wh2h_h; Bl_ = Wh2h_l; K_ = DH; kc = (c - nc0) * 32;
        } else {
            Ah_ = Ah; Al_ = Al; Bh_ = Bh; Bl_ = Bl; K_ = K; kc = c * 32;
        }
        uint32_t sA = smb + s * STAGE_BYTES;
#pragma unroll
        for (int it = 0; it < 2; ++it) {
            int i = tid + it * 256;
            int row = i >> 2, kq = i & 3;
            size_t g = (size_t)(by * 128 + row) * K_ + kc + kq * 8;
            cp16(sA + row * 80 + kq * 16, Ah_ + g);
            cp16(sA + 10240 + row * 80 + kq * 16, Al_ + g);
        }
        {
            int row = tid >> 2, kq = tid & 3;
            size_t g = (size_t)(brow0 + row) * K_ + kc + kq * 8;
            cp16(sA + 20480 + row * 80 + kq * 16, Bh_ + g);
            cp16(sA + 25600 + row * 80 + kq * 16, Bl_ + g);
        }
        asm volatile("cp.async.commit_group;" ::: "memory");
    };

    wmma::fragment<wmma::accumulator, 16, 16, 16, float> acc[2][2];
#pragma unroll
    for (int tm = 0; tm < 2; ++tm)
#pragma unroll
        for (int tn = 0; tn < 2; ++tn)
            wmma::fill_fragment(acc[tm][tn], 0.f);

    issue(0, 0);
    for (int c = 0; c < nc; ++c) {
        asm volatile("cp.async.wait_group 0;" ::: "memory");
        __syncthreads();
        if (c + 1 < nc) issue(c + 1, (c + 1) & 1);
        const bf16* sAh = (const bf16*)(smem + (c & 1) * STAGE_BYTES);
        const bf16* sAl = sAh + 128 * P_PITCH;
        const bf16* sBh = sAl + 128 * P_PITCH;
        const bf16* sBl = sBh + 64 * P_PITCH;
        GEMM_COMPUTE_CHUNK(sAh, sAl, sBh, sBl)
    }

    __syncthreads();
    float* sC = (float*)smem;
#pragma unroll
    for (int tm = 0; tm < 2; ++tm)
#pragma unroll
        for (int tn = 0; tn < 2; ++tn)
            wmma::store_matrix_sync(sC + (wm * 32 + tm * 16) * 64 + wn * 32 + tn * 16,
                                    acc[tm][tn], 64, wmma::mem_row_major);
    __syncthreads();

    if (route == 2) {   // ti
        int row = tid >> 1, c0 = (tid & 1) * 8;
        size_t gb = (size_t)(by * 128 + row) * DT + c0;
        *(float4*)(C_ti + gb)     = *(const float4*)(sC + row * 64 + c0);
        *(float4*)(C_ti + gb + 4) = *(const float4*)(sC + row * 64 + c0 + 4);
        return;
    }

    float* Cd;
    int col0;
    switch (route) {
        case 0: Cd = C_muq;  col0 = (bx & 3) * 64; break;
        case 1: Cd = C_sigq; col0 = (bx & 3) * 64; break;
        case 3: Cd = C_mup;  col0 = (bx - 9) * 64; break;
        case 4: Cd = C_sigp; col0 = (bx - 13) * 64; break;
        default: Cd = C_h;   col0 = (bx - 17) * 64; break;
    }
    const bool do_sp = (route == 4);
    const int tx = tid & 15, ty = tid >> 4;
#pragma unroll
    for (int i = 0; i < 8; ++i) {
        int row = ty * 8 + i;
        size_t gbase = (size_t)(by * 128 + row) * DZ + col0 + tx * 4;
        float4 v = *(const float4*)(sC + row * 64 + tx * 4);
        float4 o;
        o.x = do_sp ? sp_beta(v.x, 1.2f, 1.f/1.2f) : fmaxf(v.x, 0.f);
        o.y = do_sp ? sp_beta(v.y, 1.2f, 1.f/1.2f) : fmaxf(v.y, 0.f);
        o.z = do_sp ? sp_beta(v.z, 1.2f, 1.f/1.2f) : fmaxf(v.z, 0.f);
        o.w = do_sp ? sp_beta(v.w, 1.2f, 1.f/1.2f) : fmaxf(v.w, 0.f);
        *(float4*)(Cd + gbase) = o;
    }
}

// ---------------- back GEMMs: MODE 3 = r1 bf16 emit, MODE 4 = rec2 ----------
template<int MODE>
__global__ __launch_bounds__(256, 3)
void tc_gemm(const bf16* __restrict__ A0h, const bf16* __restrict__ A0l, int K0,
             const bf16* __restrict__ B0h, const bf16* __restrict__ B0l,
             float* __restrict__ C0, const float* __restrict__ aux0,
             bf16* __restrict__ Chi, bf16* __restrict__ Clo)
{
    extern __shared__ __align__(16) char smem[];
    __shared__ float red[256];

    const int tid = threadIdx.x;
    const int wid = tid >> 5;
    const int bx = blockIdx.x, by = blockIdx.y;
    const int wm = wid >> 1, wn = wid & 1;
    const int brow0 = bx * 64;
    const int nc = K0 / 32;
    const uint32_t smb = smem_u32(smem);

    auto issue = [&](int c, int s) {
        int kc = c * 32;
        uint32_t sA = smb + s * STAGE_BYTES;
#pragma unroll
        for (int it = 0; it < 2; ++it) {
            int i = tid + it * 256;
            int row = i >> 2, kq = i & 3;
            size_t g = (size_t)(by * 128 + row) * K0 + kc + kq * 8;
            cp16(sA + row * 80 + kq * 16, A0h + g);
            cp16(sA + 10240 + row * 80 + kq * 16, A0l + g);
        }
        {
            int row = tid >> 2, kq = tid & 3;
            size_t g = (size_t)(brow0 + row) * K0 + kc + kq * 8;
            cp16(sA + 20480 + row * 80 + kq * 16, B0h + g);
            cp16(sA + 25600 + row * 80 + kq * 16, B0l + g);
        }
        asm volatile("cp.async.commit_group;" ::: "memory");
    };

    wmma::fragment<wmma::accumulator, 16, 16, 16, float> acc[2][2];
#pragma unroll
    for (int tm = 0; tm < 2; ++tm)
#pragma unroll
        for (int tn = 0; tn < 2; ++tn)
            wmma::fill_fragment(acc[tm][tn], 0.f);

    issue(0, 0);
    for (int c = 0; c < nc; ++c) {
        asm volatile("cp.async.wait_group 0;" ::: "memory");
        __syncthreads();
        if (c + 1 < nc) issue(c + 1, (c + 1) & 1);
        const bf16* sAh = (const bf16*)(smem + (c & 1) * STAGE_BYTES);
        const bf16* sAl = sAh + 128 * P_PITCH;
        const bf16* sBh = sAl + 128 * P_PITCH;
        const bf16* sBl = sBh + 64 * P_PITCH;
        GEMM_COMPUTE_CHUNK(sAh, sAl, sBh, sBl)
    }

    __syncthreads();
    float* sC = (float*)smem;
#pragma unroll
    for (int tm = 0; tm < 2; ++tm)
#pragma unroll
        for (int tn = 0; tn < 2; ++tn)
            wmma::store_matrix_sync(sC + (wm * 32 + tm * 16) * 64 + wn * 32 + tn * 16,
                                    acc[tm][tn], 64, wmma::mem_row_major);
    __syncthreads();

    float lsum = 0.f;
    const int tx = tid & 15, ty = tid >> 4;
    const int N = (MODE == 4) ? 1024 : 256;
    const int col0 = bx * 64;
#pragma unroll
    for (int i = 0; i < 8; ++i) {
        int row = ty * 8 + i;
        size_t gbase = (size_t)(by * 128 + row) * N + col0 + tx * 4;
        float4 v = *(const float4*)(sC + row * 64 + tx * 4);
        if (MODE == 3) {
            __nv_bfloat162 h0 = __float22bfloat162_rn(make_float2(v.x, v.y));
            __nv_bfloat162 h1 = __float22bfloat162_rn(make_float2(v.z, v.w));
            float2 f0 = __bfloat1622float2(h0);
            float2 f1 = __bfloat1622float2(h1);
            __nv_bfloat162 l0 = __float22bfloat162_rn(make_float2(v.x - f0.x, v.y - f0.y));
            __nv_bfloat162 l1 = __float22bfloat162_rn(make_float2(v.z - f1.x, v.w - f1.y));
            *(uint32_t*)(Chi + gbase)     = *(uint32_t*)&h0;
            *(uint32_t*)(Chi + gbase + 2) = *(uint32_t*)&h1;
            *(uint32_t*)(Clo + gbase)     = *(uint32_t*)&l0;
            *(uint32_t*)(Clo + gbase + 2) = *(uint32_t*)&l1;
        } else {
            float4 a0 = *(const float4*)(aux0 + gbase);
            float4 o;
            o.x = 1.f / (1.f + expf(-v.x)); { float d = a0.x - o.x; lsum += d * d; }
            o.y = 1.f / (1.f + expf(-v.y)); { float d = a0.y - o.y; lsum += d * d; }
            o.z = 1.f / (1.f + expf(-v.z)); { float d = a0.z - o.z; lsum += d * d; }
            o.w = 1.f / (1.f + expf(-v.w)); { float d = a0.w - o.w; lsum += d * d; }
            *(float4*)(C0 + gbase) = o;
        }
    }

    if (MODE == 4) {
        red[tid] = lsum;
        __syncthreads();
#pragma unroll
        for (int s = 128; s > 0; s >>= 1) {
            if (tid < s) red[tid] += red[tid + s];
            __syncthreads();
        }
        if (tid == 0) atomicAdd(&g_acc[0], (double)red[0]);
    }
}

// ---------------- fused theta/threshold/z + z_hat + losses ------------------
__global__ __launch_bounds__(256)
void z_kernel(const float* __restrict__ theta_m_1,
              const float* __restrict__ W_vip2t,
              const float* __restrict__ W_t2z,
              const float* __restrict__ eps_z,
              const float* __restrict__ eps_zhat,
              float* __restrict__ z_out,
              float* __restrict__ zhat_out)
{
    const int R = 16;
    __shared__ float sWv[DT][DZ + 1];
    __shared__ float sSp[R][DZ + 1];
    __shared__ float sTheta[R][DT + 1];
    __shared__ float red[256];

    const int tid = threadIdx.x;
    const int row0 = blockIdx.x * R;

    for (int idx = tid; idx < DT * DZ; idx += 256) {
        int t = idx >> 8, n = idx & 255;
        sWv[t][n] = fmaxf(W_vip2t[idx], 0.f);
    }
    for (int idx = tid; idx < R * DZ; idx += 256) {
        int r = idx >> 8, n = idx & 255;
        sSp[r][n] = g_sigma_p[(size_t)(row0 + r) * DZ + n];
    }
    __syncthreads();

    {
        int r = tid >> 4, t = tid & 15;
        float dot = 0.f;
#pragma unroll 8
        for (int n = 0; n < DZ; n++)
            dot = fmaf(sSp[r][n], sWv[t][n], dot);
        size_t tix = (size_t)(row0 + r) * DT + t;
        float th_h = 0.5f * theta_m_1[tix] + 0.1f * g_ti[tix] - dot;
        float u = 0.5f * th_h;
        float sp = (u > 20.f) ? th_h : log1pf(expf(u)) * 2.0f;
        sTheta[r][t] = 0.001f * sp;
    }
    __syncthreads();

    const int n = tid;
    float wt[DT];
#pragma unroll
    for (int t = 0; t < DT; t++)
        wt[t] = fmaxf(W_t2z[(size_t)n * DT + t], 0.f);

    float e_sum = 0.f, t_sum = 0.f;
    for (int r = 0; r < R; r++) {
        float thr = 0.f;
#pragma unroll
        for (int t = 0; t < DT; t++)
            thr = fmaf(sTheta[r][t], wt[t], thr);
        thr *= 10.f;
        size_t idx = (size_t)(row0 + r) * DZ + n;
        float raw = fmaf(eps_z[idx], g_sigma_q[idx], g_mu_q[idx]);
        raw = fminf(fmaxf(raw, 0.f), 1.f);
        float zv = fmaxf(raw - thr, 0.f);
        z_out[idx] = zv;
        bf16 h = __float2bfloat16_rn(zv);
        g_z_hi[idx] = h;
        g_z_lo[idx] = __float2bfloat16_rn(zv - __bfloat162float(h));
        float zh = fmaf(eps_zhat[idx], sSp[r][n], g_mu_p[idx]);
        zhat_out[idx] = zh;
        e_sum += zv;
        float d = zv - zh;
        t_sum = fmaf(d, d, t_sum);
    }

    red[tid] = e_sum; __syncthreads();
#pragma unroll
    for (int s = 128; s > 0; s >>= 1) { if (tid < s) red[tid] += red[tid + s]; __syncthreads(); }
    if (tid == 0) atomicAdd(&g_acc[2], (double)red[0]);
    __syncthreads();
    red[tid] = t_sum; __syncthreads();
#pragma unroll
    for (int s = 128; s > 0; s >>= 1) { if (tid < s) red[tid] += red[tid + s]; __syncthreads(); }
    if (tid == 0) atomicAdd(&g_acc[1], (double)red[0]);
}

// ---------------- scalar setup / finalize -----------------------------------
__global__ void zero_acc_kernel() {
    if (threadIdx.x < 3) g_acc[threadIdx.x] = 0.0;
}

__global__ void finalize_kernel(float* __restrict__ out_scalars) {
    if (threadIdx.x == 0) {
        out_scalars[0] = (float)(g_acc[0] / (double)((size_t)BATCH * DIN));
        out_scalars[1] = (float)(g_acc[1] / (double)((size_t)BATCH * DZ));
        out_scalars[2] = (float)(g_acc[2] / (double)((size_t)BATCH * DZ));
    }
}

// ---------------- launch -----------------------------------------------------
extern "C" void kernel_launch(void* const* d_in, const int* in_sizes, int n_in,
                              void* d_out, int out_size)
{
    const float* I_t        = (const float*)d_in[0];
    const float* h_m_1      = (const float*)d_in[1];
    const float* z_m_1      = (const float*)d_in[2];
    const float* theta_m_1  = (const float*)d_in[3];
    const float* eps_z      = (const float*)d_in[4];
    const float* eps_zhat   = (const float*)d_in[5];
    const float* W_post_mu  = (const float*)d_in[6];
    const float* W_post_lv  = (const float*)d_in[7];
    const float* W_z2h      = (const float*)d_in[8];
    const float* W_h2h      = (const float*)d_in[9];
    const float* W_prior_mu = (const float*)d_in[10];
    const float* W_prior_lv = (const float*)d_in[11];
    const float* W_i2t      = (const float*)d_in[12];
    const float* W_vip2t    = (const float*)d_in[13];
    const float* W_t2z      = (const float*)d_in[14];
    const float* W_rec1     = (const float*)d_in[15];
    const float* W_rec2     = (const float*)d_in[16];

    float* out       = (float*)d_out;
    float* out_ihat  = out;
    float* out_z     = out + (size_t)BATCH * DIN;
    float* out_h     = out_z + (size_t)BATCH * DZ;
    float* out_zhat  = out_h + (size_t)BATCH * DH;
    float* out_scal  = out_zhat + (size_t)BATCH * DZ;

    float *mu_q, *sigma_q, *sigma_p, *mu_p, *ti;
    cudaGetSymbolAddress((void**)&mu_q,    g_mu_q);
    cudaGetSymbolAddress((void**)&sigma_q, g_sigma_q);
    cudaGetSymbolAddress((void**)&sigma_p, g_sigma_p);
    cudaGetSymbolAddress((void**)&mu_p,    g_mu_p);
    cudaGetSymbolAddress((void**)&ti,      g_ti);
    bf16 *It_h, *It_l, *h_h, *h_l, *zm_h, *zm_l, *z_h, *z_l, *r1_h, *r1_l;
    bf16 *Wpmu_h, *Wpmu_l, *Wplv_h, *Wplv_l, *Wz2h_h, *Wz2h_l, *Wh2h_h, *Wh2h_l;
    bf16 *Wprmu_h, *Wprmu_l, *Wprlv_h, *Wprlv_l, *Wi2t_h, *Wi2t_l;
    bf16 *Wr1_h, *Wr1_l, *Wr2_h, *Wr2_l;
    cudaGetSymbolAddress((void**)&It_h, g_It_hi);   cudaGetSymbolAddress((void**)&It_l, g_It_lo);
    cudaGetSymbolAddress((void**)&h_h,  g_h_hi);    cudaGetSymbolAddress((void**)&h_l,  g_h_lo);
    cudaGetSymbolAddress((void**)&zm_h, g_zm_hi);   cudaGetSymbolAddress((void**)&zm_l, g_zm_lo);
    cudaGetSymbolAddress((void**)&z_h,  g_z_hi);    cudaGetSymbolAddress((void**)&z_l,  g_z_lo);
    cudaGetSymbolAddress((void**)&r1_h, g_r1_hi);   cudaGetSymbolAddress((void**)&r1_l, g_r1_lo);
    cudaGetSymbolAddress((void**)&Wpmu_h, g_Wpmu_hi);   cudaGetSymbolAddress((void**)&Wpmu_l, g_Wpmu_lo);
    cudaGetSymbolAddress((void**)&Wplv_h, g_Wplv_hi);   cudaGetSymbolAddress((void**)&Wplv_l, g_Wplv_lo);
    cudaGetSymbolAddress((void**)&Wz2h_h, g_Wz2h_hi);   cudaGetSymbolAddress((void**)&Wz2h_l, g_Wz2h_lo);
    cudaGetSymbolAddress((void**)&Wh2h_h, g_Wh2h_hi);   cudaGetSymbolAddress((void**)&Wh2h_l, g_Wh2h_lo);
    cudaGetSymbolAddress((void**)&Wprmu_h, g_Wprmu_hi); cudaGetSymbolAddress((void**)&Wprmu_l, g_Wprmu_lo);
    cudaGetSymbolAddress((void**)&Wprlv_h, g_Wprlv_hi); cudaGetSymbolAddress((void**)&Wprlv_l, g_Wprlv_lo);
    cudaGetSymbolAddress((void**)&Wi2t_h, g_Wi2t_hi);   cudaGetSymbolAddress((void**)&Wi2t_l, g_Wi2t_lo);
    cudaGetSymbolAddress((void**)&Wr1_h, g_Wr1_hi);     cudaGetSymbolAddress((void**)&Wr1_l, g_Wr1_lo);
    cudaGetSymbolAddress((void**)&Wr2_h, g_Wr2_hi);     cudaGetSymbolAddress((void**)&Wr2_l, g_Wr2_lo);

    cudaFuncSetAttribute(gemm_front, cudaFuncAttributeMaxDynamicSharedMemorySize, SMEM_TOTAL_BYTES);
    cudaFuncSetAttribute(tc_gemm<3>, cudaFuncAttributeMaxDynamicSharedMemorySize, SMEM_TOTAL_BYTES);
    cudaFuncSetAttribute(tc_gemm<4>, cudaFuncAttributeMaxDynamicSharedMemorySize, SMEM_TOTAL_BYTES);

    const dim3 blk(256);
    zero_acc_kernel<<<1, 32>>>();

    cvt_all<<<(CVT_TOTAL + 1023) / 1024, blk>>>(
        (const float4*)I_t, (const float4*)h_m_1, (const float4*)z_m_1,
        (const float4*)W_post_mu, (const float4*)W_post_lv,
        (const float4*)W_z2h, (const float4*)W_h2h,
        (const float4*)W_prior_mu, (const float4*)W_prior_lv,
        (const float4*)W_i2t, (const float4*)W_rec1, (const float4*)W_rec2);

    // all front GEMMs in one wave
    gemm_front<<<dim3(21, BATCH / 128), blk, SMEM_TOTAL_BYTES>>>(
        It_h, It_l, h_h, h_l, zm_h, zm_l,
        Wpmu_h, Wpmu_l, Wplv_h, Wplv_l, Wi2t_h, Wi2t_l,
        Wprmu_h, Wprmu_l, Wprlv_h, Wprlv_l,
        Wz2h_h, Wz2h_l, Wh2h_h, Wh2h_l,
        mu_q, sigma_q, ti, mu_p, sigma_p, out_h);

    z_kernel<<<BATCH / 16, blk>>>(theta_m_1, W_vip2t, W_t2z, eps_z, eps_zhat,
                                  out_z, out_zhat);

    tc_gemm<3><<<dim3(4, BATCH / 128), blk, SMEM_TOTAL_BYTES>>>(
        z_h, z_l, DZ, Wr1_h, Wr1_l, nullptr, nullptr, r1_h, r1_l);

    tc_gemm<4><<<dim3(16, BATCH / 128), blk, SMEM_TOTAL_BYTES>>>(
        r1_h, r1_l, DREC, Wr2_h, Wr2_l, out_ihat, I_t, nullptr, nullptr);

    finalize_kernel<<<1, 32>>>(out_scal);
    (void)in_sizes; (void)n_in; (void)out_size;
}

// round 6
// speedup vs baseline: 3.0874x; 1.4701x over previous
#include <cuda_runtime.h>
#include <cuda_fp16.h>
#include <mma.h>
#include <math.h>
#include <stdint.h>

using namespace nvcuda;

#define BATCH 8192
#define DIN   1024
#define DZ    256
#define DH    256
#define DT    16
#define DREC  256

// ---------------- scratch (device globals) ----------------------------------
__device__ float g_mu_q   [BATCH * DZ];
__device__ float g_sigma_q[BATCH * DZ];
__device__ float g_sigma_p[BATCH * DZ];
__device__ float g_mu_p   [BATCH * DZ];
__device__ float g_ti     [BATCH * DT];
__device__ double g_acc[3];

// fp16: activations hi-only, weights hi+lo
__device__ half g_It_hi [BATCH * DIN];
__device__ half g_h_hi  [BATCH * DH];
__device__ half g_zm_hi [BATCH * DZ];
__device__ half g_z_hi  [BATCH * DZ];
__device__ half g_r1_hi [BATCH * DREC];
__device__ half g_Wpmu_hi [DZ * DIN],  g_Wpmu_lo [DZ * DIN];
__device__ half g_Wplv_hi [DZ * DIN],  g_Wplv_lo [DZ * DIN];
__device__ half g_Wz2h_hi [DH * DZ],   g_Wz2h_lo [DH * DZ];
__device__ half g_Wh2h_hi [DH * DH],   g_Wh2h_lo [DH * DH];
__device__ half g_Wprmu_hi[DZ * DH],   g_Wprmu_lo[DZ * DH];
__device__ half g_Wprlv_hi[DZ * DH],   g_Wprlv_lo[DZ * DH];
__device__ half g_Wi2t_hi [64 * DIN],  g_Wi2t_lo [64 * DIN];   // padded 16->64
__device__ half g_Wr1_hi  [DREC * DZ], g_Wr1_lo  [DREC * DZ];
__device__ half g_Wr2_hi  [DIN * DREC], g_Wr2_lo [DIN * DREC];

// ---------------- helpers ----------------------------------------------------
__device__ __forceinline__ float sp_beta(float x, float beta, float invb) {
    float t = beta * x;
    if (t > 20.f) return x;
    return log1pf(expf(t)) * invb;
}

__device__ __forceinline__ uint32_t smem_u32(const void* p) {
    uint32_t a;
    asm("{ .reg .u64 t; cvta.to.shared.u64 t, %1; cvt.u32.u64 %0, t; }" : "=r"(a) : "l"(p));
    return a;
}

__device__ __forceinline__ void cp16(uint32_t dst, const void* src) {
    asm volatile("cp.async.cg.shared.global [%0], [%1], 16;" :: "r"(dst), "l"(src));
}

__device__ __forceinline__ void cvt_store2(float4 v, half* hi, half* lo, size_t e) {
    half2 h0 = __floats2half2_rn(v.x, v.y);
    half2 h1 = __floats2half2_rn(v.z, v.w);
    float2 f0 = __half22float2(h0);
    float2 f1 = __half22float2(h1);
    half2 l0 = __floats2half2_rn(v.x - f0.x, v.y - f0.y);
    half2 l1 = __floats2half2_rn(v.z - f1.x, v.w - f1.y);
    uint2 hv, lv;
    hv.x = *(uint32_t*)&h0; hv.y = *(uint32_t*)&h1;
    lv.x = *(uint32_t*)&l0; lv.y = *(uint32_t*)&l1;
    *(uint2*)(hi + e) = hv;
    *(uint2*)(lo + e) = lv;
}

__device__ __forceinline__ void cvt_store1(float4 v, half* hi, size_t e) {
    half2 h0 = __floats2half2_rn(v.x, v.y);
    half2 h1 = __floats2half2_rn(v.z, v.w);
    uint2 hv;
    hv.x = *(uint32_t*)&h0; hv.y = *(uint32_t*)&h1;
    *(uint2*)(hi + e) = hv;
}

// ---------------- batched fp32 -> fp16 conversion ----------------------------
#define S_IT    2097152
#define S_H     524288
#define S_ZM    524288
#define S_W256  65536
#define S_W64   16384
#define S_WI2T  4096
#define S_PAD   12288
#define CVT_TOTAL (S_IT + S_H + S_ZM + 3*S_W256 + 6*S_W64 + S_WI2T + S_PAD)

__device__ __forceinline__ void cvt_one(long o,
    const float4* It, const float4* h, const float4* zm,
    const float4* Wpmu, const float4* Wplv, const float4* Wz2h, const float4* Wh2h,
    const float4* Wprmu, const float4* Wprlv, const float4* Wi2t,
    const float4* Wr1, const float4* Wr2)
{
    if (o < S_IT)   { cvt_store1(It[o], g_It_hi, (size_t)o*4); return; }  o -= S_IT;
    if (o < S_H)    { cvt_store1(h[o],  g_h_hi,  (size_t)o*4); return; }  o -= S_H;
    if (o < S_ZM)   { cvt_store1(zm[o], g_zm_hi, (size_t)o*4); return; }  o -= S_ZM;
    if (o < S_W256) { cvt_store2(Wpmu[o], g_Wpmu_hi, g_Wpmu_lo, (size_t)o*4); return; }  o -= S_W256;
    if (o < S_W256) { cvt_store2(Wplv[o], g_Wplv_hi, g_Wplv_lo, (size_t)o*4); return; }  o -= S_W256;
    if (o < S_W64)  { cvt_store2(Wz2h[o], g_Wz2h_hi, g_Wz2h_lo, (size_t)o*4); return; }  o -= S_W64;
    if (o < S_W64)  { cvt_store2(Wh2h[o], g_Wh2h_hi, g_Wh2h_lo, (size_t)o*4); return; }  o -= S_W64;
    if (o < S_W64)  { cvt_store2(Wprmu[o], g_Wprmu_hi, g_Wprmu_lo, (size_t)o*4); return; } o -= S_W64;
    if (o < S_W64)  { cvt_store2(Wprlv[o], g_Wprlv_hi, g_Wprlv_lo, (size_t)o*4); return; } o -= S_W64;
    if (o < S_WI2T) { cvt_store2(Wi2t[o], g_Wi2t_hi, g_Wi2t_lo, (size_t)o*4); return; }  o -= S_WI2T;
    if (o < S_PAD)  {
        size_t e = (size_t)(S_WI2T + o) * 4;
        uint2 z = make_uint2(0u, 0u);
        *(uint2*)(g_Wi2t_hi + e) = z;
        *(uint2*)(g_Wi2t_lo + e) = z;
        return;
    }               o -= S_PAD;
    if (o < S_W64)  { cvt_store2(Wr1[o], g_Wr1_hi, g_Wr1_lo, (size_t)o*4); return; }  o -= S_W64;
    if (o < S_W256) { cvt_store2(Wr2[o], g_Wr2_hi, g_Wr2_lo, (size_t)o*4); }
}

__global__ __launch_bounds__(256)
void cvt_all(const float4* __restrict__ It, const float4* __restrict__ h,
             const float4* __restrict__ zm,
             const float4* __restrict__ Wpmu, const float4* __restrict__ Wplv,
             const float4* __restrict__ Wz2h, const float4* __restrict__ Wh2h,
             const float4* __restrict__ Wprmu, const float4* __restrict__ Wprlv,
             const float4* __restrict__ Wi2t, const float4* __restrict__ Wr1,
             const float4* __restrict__ Wr2)
{
    const long stride = (long)gridDim.x * 256;
    long i = (long)blockIdx.x * 256 + threadIdx.x;
#pragma unroll
    for (int u = 0; u < 4; ++u, i += stride)
        if (i < CVT_TOTAL)
            cvt_one(i, It, h, zm, Wpmu, Wplv, Wz2h, Wh2h, Wprmu, Wprlv, Wi2t, Wr1, Wr2);
}

// ============================================================================
// GEMM: fp16 2-term (A_hi*B_hi + A_hi*B_lo). BM=128, BN=64, BK=32, 256 thr.
// ============================================================================
#define P_PITCH 40
#define STAGE_BYTES 20480          // A_hi 10240 | B_hi 5120 | B_lo 5120
#define OFF_BHI 10240
#define OFF_BLO 15360
#define SMEM_TOTAL_BYTES 40960     // 2 stages; epilogue sC (32KB) reuses

#define GEMM_COMPUTE_CHUNK(sAh_, sBh_, sBl_)                                              \
    _Pragma("unroll")                                                                      \
    for (int ks = 0; ks < 2; ++ks) {                                                       \
        wmma::fragment<wmma::matrix_a, 16, 16, 16, half, wmma::row_major> fa[2];           \
        wmma::fragment<wmma::matrix_b, 16, 16, 16, half, wmma::col_major> fb[2];           \
        _Pragma("unroll")                                                                  \
        for (int tm = 0; tm < 2; ++tm)                                                     \
            wmma::load_matrix_sync(fa[tm], sAh_ + (wm * 32 + tm * 16) * P_PITCH + ks * 16, P_PITCH); \
        _Pragma("unroll")                                                                  \
        for (int tn = 0; tn < 2; ++tn)                                                     \
            wmma::load_matrix_sync(fb[tn], sBh_ + (wn * 32 + tn * 16) * P_PITCH + ks * 16, P_PITCH); \
        _Pragma("unroll")                                                                  \
        for (int tm = 0; tm < 2; ++tm)                                                     \
            _Pragma("unroll")                                                              \
            for (int tn = 0; tn < 2; ++tn)                                                 \
                wmma::mma_sync(acc[tm][tn], fa[tm], fb[tn], acc[tm][tn]);                  \
        {                                                                                  \
            wmma::fragment<wmma::matrix_b, 16, 16, 16, half, wmma::col_major> fbl[2];      \
            _Pragma("unroll")                                                              \
            for (int tn = 0; tn < 2; ++tn)                                                 \
                wmma::load_matrix_sync(fbl[tn], sBl_ + (wn * 32 + tn * 16) * P_PITCH + ks * 16, P_PITCH); \
            _Pragma("unroll")                                                              \
            for (int tm = 0; tm < 2; ++tm)                                                 \
                _Pragma("unroll")                                                          \
                for (int tn = 0; tn < 2; ++tn)                                             \
                    wmma::mma_sync(acc[tm][tn], fa[tm], fbl[tn], acc[tm][tn]);             \
        }                                                                                  \
    }

// ---------------- front mega-GEMM -------------------------------------------
// bx 0-3 mu_q | 4-7 sigma_q | 8 ti | 9-12 mu_p | 13-16 sigma_p | 17-20 h(dual)
__global__ __launch_bounds__(256, 3)
void gemm_front(const half* __restrict__ It_h, const half* __restrict__ hm_h,
                const half* __restrict__ zm_h,
                const half* __restrict__ Wpmu_h, const half* __restrict__ Wpmu_l,
                const half* __restrict__ Wplv_h, const half* __restrict__ Wplv_l,
                const half* __restrict__ Wi2t_h, const half* __restrict__ Wi2t_l,
                const half* __restrict__ Wprmu_h, const half* __restrict__ Wprmu_l,
                const half* __restrict__ Wprlv_h, const half* __restrict__ Wprlv_l,
                const half* __restrict__ Wz2h_h, const half* __restrict__ Wz2h_l,
                const half* __restrict__ Wh2h_h, const half* __restrict__ Wh2h_l,
                float* __restrict__ C_muq, float* __restrict__ C_sigq,
                float* __restrict__ C_ti,  float* __restrict__ C_mup,
                float* __restrict__ C_sigp, float* __restrict__ C_h)
{
    extern __shared__ __align__(16) char smem[];
    const int tid = threadIdx.x;
    const int wid = tid >> 5;
    const int bx = blockIdx.x, by = blockIdx.y;
    const int wm = wid >> 1, wn = wid & 1;

    int route;
    if (bx < 4) route = 0; else if (bx < 8) route = 1; else if (bx == 8) route = 2;
    else if (bx < 13) route = 3; else if (bx < 17) route = 4; else route = 5;

    const half *Ah, *Bh, *Bl;
    int K, brow0;
    switch (route) {
        case 0: Ah = It_h; Bh = Wpmu_h; Bl = Wpmu_l; K = DIN; brow0 = (bx & 3) * 64; break;
        case 1: Ah = It_h; Bh = Wplv_h; Bl = Wplv_l; K = DIN; brow0 = (bx & 3) * 64; break;
        case 2: Ah = It_h; Bh = Wi2t_h; Bl = Wi2t_l; K = DIN; brow0 = 0; break;
        case 3: Ah = hm_h; Bh = Wprmu_h; Bl = Wprmu_l; K = DH; brow0 = (bx - 9) * 64; break;
        case 4: Ah = hm_h; Bh = Wprlv_h; Bl = Wprlv_l; K = DH; brow0 = (bx - 13) * 64; break;
        default: Ah = zm_h; Bh = Wz2h_h; Bl = Wz2h_l; K = DZ; brow0 = (bx - 17) * 64; break;
    }
    const int nc0 = K / 32;
    const int nc = (route == 5) ? nc0 + DH / 32 : nc0;

    const uint32_t smb = smem_u32(smem);

    auto issue = [&](int c, int s) {
        const half *Ah_, *Bh_, *Bl_;
        int K_, kc;
        if (route == 5 && c >= nc0) {
            Ah_ = hm_h; Bh_ = Wh2h_h; Bl_ = Wh2h_l; K_ = DH; kc = (c - nc0) * 32;
        } else {
            Ah_ = Ah; Bh_ = Bh; Bl_ = Bl; K_ = K; kc = c * 32;
        }
        uint32_t sA = smb + s * STAGE_BYTES;
#pragma unroll
        for (int it = 0; it < 2; ++it) {
            int i = tid + it * 256;
            int row = i >> 2, kq = i & 3;
            cp16(sA + row * 80 + kq * 16,
                 Ah_ + (size_t)(by * 128 + row) * K_ + kc + kq * 8);
        }
        {
            int row = tid >> 2, kq = tid & 3;
            size_t g = (size_t)(brow0 + row) * K_ + kc + kq * 8;
            cp16(sA + OFF_BHI + row * 80 + kq * 16, Bh_ + g);
            cp16(sA + OFF_BLO + row * 80 + kq * 16, Bl_ + g);
        }
        asm volatile("cp.async.commit_group;" ::: "memory");
    };

    wmma::fragment<wmma::accumulator, 16, 16, 16, float> acc[2][2];
#pragma unroll
    for (int tm = 0; tm < 2; ++tm)
#pragma unroll
        for (int tn = 0; tn < 2; ++tn)
            wmma::fill_fragment(acc[tm][tn], 0.f);

    issue(0, 0);
    for (int c = 0; c < nc; ++c) {
        asm volatile("cp.async.wait_group 0;" ::: "memory");
        __syncthreads();
        if (c + 1 < nc) issue(c + 1, (c + 1) & 1);
        const half* sAh = (const half*)(smem + (c & 1) * STAGE_BYTES);
        const half* sBh = (const half*)(smem + (c & 1) * STAGE_BYTES + OFF_BHI);
        const half* sBl = (const half*)(smem + (c & 1) * STAGE_BYTES + OFF_BLO);
        GEMM_COMPUTE_CHUNK(sAh, sBh, sBl)
    }

    __syncthreads();
    float* sC = (float*)smem;
#pragma unroll
    for (int tm = 0; tm < 2; ++tm)
#pragma unroll
        for (int tn = 0; tn < 2; ++tn)
            wmma::store_matrix_sync(sC + (wm * 32 + tm * 16) * 64 + wn * 32 + tn * 16,
                                    acc[tm][tn], 64, wmma::mem_row_major);
    __syncthreads();

    if (route == 2) {   // ti
        int row = tid >> 1, c0 = (tid & 1) * 8;
        size_t gb = (size_t)(by * 128 + row) * DT + c0;
        *(float4*)(C_ti + gb)     = *(const float4*)(sC + row * 64 + c0);
        *(float4*)(C_ti + gb + 4) = *(const float4*)(sC + row * 64 + c0 + 4);
        return;
    }

    float* Cd;
    int col0;
    switch (route) {
        case 0: Cd = C_muq;  col0 = (bx & 3) * 64; break;
        case 1: Cd = C_sigq; col0 = (bx & 3) * 64; break;
        case 3: Cd = C_mup;  col0 = (bx - 9) * 64; break;
        case 4: Cd = C_sigp; col0 = (bx - 13) * 64; break;
        default: Cd = C_h;   col0 = (bx - 17) * 64; break;
    }
    const bool do_sp = (route == 4);
    const int tx = tid & 15, ty = tid >> 4;
#pragma unroll
    for (int i = 0; i < 8; ++i) {
        int row = ty * 8 + i;
        size_t gbase = (size_t)(by * 128 + row) * DZ + col0 + tx * 4;
        float4 v = *(const float4*)(sC + row * 64 + tx * 4);
        float4 o;
        o.x = do_sp ? sp_beta(v.x, 1.2f, 1.f/1.2f) : fmaxf(v.x, 0.f);
        o.y = do_sp ? sp_beta(v.y, 1.2f, 1.f/1.2f) : fmaxf(v.y, 0.f);
        o.z = do_sp ? sp_beta(v.z, 1.2f, 1.f/1.2f) : fmaxf(v.z, 0.f);
        o.w = do_sp ? sp_beta(v.w, 1.2f, 1.f/1.2f) : fmaxf(v.w, 0.f);
        *(float4*)(Cd + gbase) = o;
    }
}

// ---------------- back GEMMs: MODE 3 = r1 fp16 emit, MODE 4 = rec2 ----------
template<int MODE>
__global__ __launch_bounds__(256, 3)
void tc_gemm(const half* __restrict__ A0h, int K0,
             const half* __restrict__ B0h, const half* __restrict__ B0l,
             float* __restrict__ C0, const float* __restrict__ aux0,
             half* __restrict__ Chi)
{
    extern __shared__ __align__(16) char smem[];
    __shared__ float red[256];

    const int tid = threadIdx.x;
    const int wid = tid >> 5;
    const int bx = blockIdx.x, by = blockIdx.y;
    const int wm = wid >> 1, wn = wid & 1;
    const int brow0 = bx * 64;
    const int nc = K0 / 32;
    const uint32_t smb = smem_u32(smem);

    auto issue = [&](int c, int s) {
        int kc = c * 32;
        uint32_t sA = smb + s * STAGE_BYTES;
#pragma unroll
        for (int it = 0; it < 2; ++it) {
            int i = tid + it * 256;
            int row = i >> 2, kq = i & 3;
            cp16(sA + row * 80 + kq * 16,
                 A0h + (size_t)(by * 128 + row) * K0 + kc + kq * 8);
        }
        {
            int row = tid >> 2, kq = tid & 3;
            size_t g = (size_t)(brow0 + row) * K0 + kc + kq * 8;
            cp16(sA + OFF_BHI + row * 80 + kq * 16, B0h + g);
            cp16(sA + OFF_BLO + row * 80 + kq * 16, B0l + g);
        }
        asm volatile("cp.async.commit_group;" ::: "memory");
    };

    wmma::fragment<wmma::accumulator, 16, 16, 16, float> acc[2][2];
#pragma unroll
    for (int tm = 0; tm < 2; ++tm)
#pragma unroll
        for (int tn = 0; tn < 2; ++tn)
            wmma::fill_fragment(acc[tm][tn], 0.f);

    issue(0, 0);
    for (int c = 0; c < nc; ++c) {
        asm volatile("cp.async.wait_group 0;" ::: "memory");
        __syncthreads();
        if (c + 1 < nc) issue(c + 1, (c + 1) & 1);
        const half* sAh = (const half*)(smem + (c & 1) * STAGE_BYTES);
        const half* sBh = (const half*)(smem + (c & 1) * STAGE_BYTES + OFF_BHI);
        const half* sBl = (const half*)(smem + (c & 1) * STAGE_BYTES + OFF_BLO);
        GEMM_COMPUTE_CHUNK(sAh, sBh, sBl)
    }

    __syncthreads();
    float* sC = (float*)smem;
#pragma unroll
    for (int tm = 0; tm < 2; ++tm)
#pragma unroll
        for (int tn = 0; tn < 2; ++tn)
            wmma::store_matrix_sync(sC + (wm * 32 + tm * 16) * 64 + wn * 32 + tn * 16,
                                    acc[tm][tn], 64, wmma::mem_row_major);
    __syncthreads();

    float lsum = 0.f;
    const int tx = tid & 15, ty = tid >> 4;
    const int N = (MODE == 4) ? 1024 : 256;
    const int col0 = bx * 64;
#pragma unroll
    for (int i = 0; i < 8; ++i) {
        int row = ty * 8 + i;
        size_t gbase = (size_t)(by * 128 + row) * N + col0 + tx * 4;
        float4 v = *(const float4*)(sC + row * 64 + tx * 4);
        if (MODE == 3) {
            half2 h0 = __floats2half2_rn(v.x, v.y);
            half2 h1 = __floats2half2_rn(v.z, v.w);
            uint2 u;
            u.x = *(uint32_t*)&h0; u.y = *(uint32_t*)&h1;
            *(uint2*)(Chi + gbase) = u;
        } else {
            float4 a0 = *(const float4*)(aux0 + gbase);
            float4 o;
            o.x = 1.f / (1.f + expf(-v.x)); { float d = a0.x - o.x; lsum += d * d; }
            o.y = 1.f / (1.f + expf(-v.y)); { float d = a0.y - o.y; lsum += d * d; }
            o.z = 1.f / (1.f + expf(-v.z)); { float d = a0.z - o.z; lsum += d * d; }
            o.w = 1.f / (1.f + expf(-v.w)); { float d = a0.w - o.w; lsum += d * d; }
            *(float4*)(C0 + gbase) = o;
        }
    }

    if (MODE == 4) {
        red[tid] = lsum;
        __syncthreads();
#pragma unroll
        for (int s = 128; s > 0; s >>= 1) {
            if (tid < s) red[tid] += red[tid + s];
            __syncthreads();
        }
        if (tid == 0) atomicAdd(&g_acc[0], (double)red[0]);
    }
}

// ---------------- fused theta/threshold/z + z_hat + losses (vectorized) -----
__global__ __launch_bounds__(256)
void z_kernel(const float* __restrict__ theta_m_1,
              const float* __restrict__ W_vip2t,
              const float* __restrict__ W_t2z,
              const float* __restrict__ eps_z,
              const float* __restrict__ eps_zhat,
              float* __restrict__ z_out,
              float* __restrict__ zhat_out)
{
    const int R = 16;
    __shared__ float sWv[DT][DZ + 1];     // relu(W_vip2t)
    __shared__ float sSp[R][260];         // sigma_p rows (float4-aligned pitch)
    __shared__ float sWt[DT][260];        // relu(W_t2z) transposed: [t][n]
    __shared__ float sTheta[R][DT + 1];
    __shared__ float red[256];

    const int tid = threadIdx.x;
    const int row0 = blockIdx.x * R;

    for (int idx = tid; idx < DT * DZ; idx += 256) {
        int t = idx >> 8, n = idx & 255;
        sWv[t][n] = fmaxf(W_vip2t[idx], 0.f);
    }
    for (int idx = tid; idx < DZ * DT; idx += 256) {
        int n = idx >> 4, t = idx & 15;   // coalesced read of W_t2z[n*16+t]
        sWt[t][n] = fmaxf(W_t2z[idx], 0.f);
    }
    for (int idx = tid; idx < R * DZ; idx += 256) {
        int r = idx >> 8, n = idx & 255;
        sSp[r][n] = g_sigma_p[(size_t)(row0 + r) * DZ + n];
    }
    __syncthreads();

    {   // theta: 16 rows x 16 t
        int r = tid >> 4, t = tid & 15;
        float dot = 0.f;
#pragma unroll 8
        for (int n = 0; n < DZ; n++)
            dot = fmaf(sSp[r][n], sWv[t][n], dot);
        size_t tix = (size_t)(row0 + r) * DT + t;
        float th_h = 0.5f * theta_m_1[tix] + 0.1f * g_ti[tix] - dot;
        float u = 0.5f * th_h;
        float sp = (u > 20.f) ? th_h : log1pf(expf(u)) * 2.0f;
        sTheta[r][t] = 0.001f * sp;
    }
    __syncthreads();

    // main: 4 passes, each 4 rows x 64 col-quads, fully float4
    const int q = tid & 63;       // column quad
    const int rb = tid >> 6;      // row within pass
    float e_sum = 0.f, t_sum = 0.f;

#pragma unroll
    for (int p = 0; p < 4; ++p) {
        const int r = rb + p * 4;
        const size_t idx = (size_t)(row0 + r) * DZ + q * 4;

        float4 muq = *(const float4*)(g_mu_q + idx);
        float4 sgq = *(const float4*)(g_sigma_q + idx);
        float4 epz = *(const float4*)(eps_z + idx);
        float4 eph = *(const float4*)(eps_zhat + idx);
        float4 mup = *(const float4*)(g_mu_p + idx);
        float4 sp4 = *(const float4*)(&sSp[r][q * 4]);

        float4 thr = make_float4(0.f, 0.f, 0.f, 0.f);
#pragma unroll
        for (int t = 0; t < DT; ++t) {
            float th = sTheta[r][t];
            float4 w = *(const float4*)(&sWt[t][q * 4]);
            thr.x = fmaf(th, w.x, thr.x);
            thr.y = fmaf(th, w.y, thr.y);
            thr.z = fmaf(th, w.z, thr.z);
            thr.w = fmaf(th, w.w, thr.w);
        }

        float4 zv, zh;
        {
            float raw = fminf(fmaxf(fmaf(epz.x, sgq.x, muq.x), 0.f), 1.f);
            zv.x = fmaxf(raw - 10.f * thr.x, 0.f);
            zh.x = fmaf(eph.x, sp4.x, mup.x);
            raw = fminf(fmaxf(fmaf(epz.y, sgq.y, muq.y), 0.f), 1.f);
            zv.y = fmaxf(raw - 10.f * thr.y, 0.f);
            zh.y = fmaf(eph.y, sp4.y, mup.y);
            raw = fminf(fmaxf(fmaf(epz.z, sgq.z, muq.z), 0.f), 1.f);
            zv.z = fmaxf(raw - 10.f * thr.z, 0.f);
            zh.z = fmaf(eph.z, sp4.z, mup.z);
            raw = fminf(fmaxf(fmaf(epz.w, sgq.w, muq.w), 0.f), 1.f);
            zv.w = fmaxf(raw - 10.f * thr.w, 0.f);
            zh.w = fmaf(eph.w, sp4.w, mup.w);
        }

        *(float4*)(z_out + idx) = zv;
        *(float4*)(zhat_out + idx) = zh;
        {
            half2 h0 = __floats2half2_rn(zv.x, zv.y);
            half2 h1 = __floats2half2_rn(zv.z, zv.w);
            uint2 u;
            u.x = *(uint32_t*)&h0; u.y = *(uint32_t*)&h1;
            *(uint2*)(g_z_hi + idx) = u;
        }

        e_sum += zv.x + zv.y + zv.z + zv.w;
        float d;
        d = zv.x - zh.x; t_sum = fmaf(d, d, t_sum);
        d = zv.y - zh.y; t_sum = fmaf(d, d, t_sum);
        d = zv.z - zh.z; t_sum = fmaf(d, d, t_sum);
        d = zv.w - zh.w; t_sum = fmaf(d, d, t_sum);
    }

    red[tid] = e_sum; __syncthreads();
#pragma unroll
    for (int s = 128; s > 0; s >>= 1) { if (tid < s) red[tid] += red[tid + s]; __syncthreads(); }
    if (tid == 0) atomicAdd(&g_acc[2], (double)red[0]);
    __syncthreads();
    red[tid] = t_sum; __syncthreads();
#pragma unroll
    for (int s = 128; s > 0; s >>= 1) { if (tid < s) red[tid] += red[tid + s]; __syncthreads(); }
    if (tid == 0) atomicAdd(&g_acc[1], (double)red[0]);
}

// ---------------- scalar setup / finalize -----------------------------------
__global__ void zero_acc_kernel() {
    if (threadIdx.x < 3) g_acc[threadIdx.x] = 0.0;
}

__global__ void finalize_kernel(float* __restrict__ out_scalars) {
    if (threadIdx.x == 0) {
        out_scalars[0] = (float)(g_acc[0] / (double)((size_t)BATCH * DIN));
        out_scalars[1] = (float)(g_acc[1] / (double)((size_t)BATCH * DZ));
        out_scalars[2] = (float)(g_acc[2] / (double)((size_t)BATCH * DZ));
    }
}

// ---------------- launch -----------------------------------------------------
extern "C" void kernel_launch(void* const* d_in, const int* in_sizes, int n_in,
                              void* d_out, int out_size)
{
    const float* I_t        = (const float*)d_in[0];
    const float* h_m_1      = (const float*)d_in[1];
    const float* z_m_1      = (const float*)d_in[2];
    const float* theta_m_1  = (const float*)d_in[3];
    const float* eps_z      = (const float*)d_in[4];
    const float* eps_zhat   = (const float*)d_in[5];
    const float* W_post_mu  = (const float*)d_in[6];
    const float* W_post_lv  = (const float*)d_in[7];
    const float* W_z2h      = (const float*)d_in[8];
    const float* W_h2h      = (const float*)d_in[9];
    const float* W_prior_mu = (const float*)d_in[10];
    const float* W_prior_lv = (const float*)d_in[11];
    const float* W_i2t      = (const float*)d_in[12];
    const float* W_vip2t    = (const float*)d_in[13];
    const float* W_t2z      = (const float*)d_in[14];
    const float* W_rec1     = (const float*)d_in[15];
    const float* W_rec2     = (const float*)d_in[16];

    float* out       = (float*)d_out;
    float* out_ihat  = out;
    float* out_z     = out + (size_t)BATCH * DIN;
    float* out_h     = out_z + (size_t)BATCH * DZ;
    float* out_zhat  = out_h + (size_t)BATCH * DH;
    float* out_scal  = out_zhat + (size_t)BATCH * DZ;

    float *mu_q, *sigma_q, *sigma_p, *mu_p, *ti;
    cudaGetSymbolAddress((void**)&mu_q,    g_mu_q);
    cudaGetSymbolAddress((void**)&sigma_q, g_sigma_q);
    cudaGetSymbolAddress((void**)&sigma_p, g_sigma_p);
    cudaGetSymbolAddress((void**)&mu_p,    g_mu_p);
    cudaGetSymbolAddress((void**)&ti,      g_ti);
    half *It_h, *h_h, *zm_h, *z_h, *r1_h;
    half *Wpmu_h, *Wpmu_l, *Wplv_h, *Wplv_l, *Wz2h_h, *Wz2h_l, *Wh2h_h, *Wh2h_l;
    half *Wprmu_h, *Wprmu_l, *Wprlv_h, *Wprlv_l, *Wi2t_h, *Wi2t_l;
    half *Wr1_h, *Wr1_l, *Wr2_h, *Wr2_l;
    cudaGetSymbolAddress((void**)&It_h, g_It_hi);
    cudaGetSymbolAddress((void**)&h_h,  g_h_hi);
    cudaGetSymbolAddress((void**)&zm_h, g_zm_hi);
    cudaGetSymbolAddress((void**)&z_h,  g_z_hi);
    cudaGetSymbolAddress((void**)&r1_h, g_r1_hi);
    cudaGetSymbolAddress((void**)&Wpmu_h, g_Wpmu_hi);   cudaGetSymbolAddress((void**)&Wpmu_l, g_Wpmu_lo);
    cudaGetSymbolAddress((void**)&Wplv_h, g_Wplv_hi);   cudaGetSymbolAddress((void**)&Wplv_l, g_Wplv_lo);
    cudaGetSymbolAddress((void**)&Wz2h_h, g_Wz2h_hi);   cudaGetSymbolAddress((void**)&Wz2h_l, g_Wz2h_lo);
    cudaGetSymbolAddress((void**)&Wh2h_h, g_Wh2h_hi);   cudaGetSymbolAddress((void**)&Wh2h_l, g_Wh2h_lo);
    cudaGetSymbolAddress((void**)&Wprmu_h, g_Wprmu_hi); cudaGetSymbolAddress((void**)&Wprmu_l, g_Wprmu_lo);
    cudaGetSymbolAddress((void**)&Wprlv_h, g_Wprlv_hi); cudaGetSymbolAddress((void**)&Wprlv_l, g_Wprlv_lo);
    cudaGetSymbolAddress((void**)&Wi2t_h, g_Wi2t_hi);   cudaGetSymbolAddress((void**)&Wi2t_l, g_Wi2t_lo);
    cudaGetSymbolAddress((void**)&Wr1_h, g_Wr1_hi);     cudaGetSymbolAddress((void**)&Wr1_l, g_Wr1_lo);
    cudaGetSymbolAddress((void**)&Wr2_h, g_Wr2_hi);     cudaGetSymbolAddress((void**)&Wr2_l, g_Wr2_lo);

    cudaFuncSetAttribute(gemm_front, cudaFuncAttributeMaxDynamicSharedMemorySize, SMEM_TOTAL_BYTES);
    cudaFuncSetAttribute(tc_gemm<3>, cudaFuncAttributeMaxDynamicSharedMemorySize, SMEM_TOTAL_BYTES);
    cudaFuncSetAttribute(tc_gemm<4>, cudaFuncAttributeMaxDynamicSharedMemorySize, SMEM_TOTAL_BYTES);

    const dim3 blk(256);
    zero_acc_kernel<<<1, 32>>>();

    cvt_all<<<(CVT_TOTAL + 1023) / 1024, blk>>>(
        (const float4*)I_t, (const float4*)h_m_1, (const float4*)z_m_1,
        (const float4*)W_post_mu, (const float4*)W_post_lv,
        (const float4*)W_z2h, (const float4*)W_h2h,
        (const float4*)W_prior_mu, (const float4*)W_prior_lv,
        (const float4*)W_i2t, (const float4*)W_rec1, (const float4*)W_rec2);

    gemm_front<<<dim3(21, BATCH / 128), blk, SMEM_TOTAL_BYTES>>>(
        It_h, h_h, zm_h,
        Wpmu_h, Wpmu_l, Wplv_h, Wplv_l, Wi2t_h, Wi2t_l,
        Wprmu_h, Wprmu_l, Wprlv_h, Wprlv_l,
        Wz2h_h, Wz2h_l, Wh2h_h, Wh2h_l,
        mu_q, sigma_q, ti, mu_p, sigma_p, out_h);

    z_kernel<<<BATCH / 16, blk>>>(theta_m_1, W_vip2t, W_t2z, eps_z, eps_zhat,
                                  out_z, out_zhat);

    tc_gemm<3><<<dim3(4, BATCH / 128), blk, SMEM_TOTAL_BYTES>>>(
        z_h, DZ, Wr1_h, Wr1_l, nullptr, nullptr, r1_h);

    tc_gemm<4><<<dim3(16, BATCH / 128), blk, SMEM_TOTAL_BYTES>>>(
        r1_h, DREC, Wr2_h, Wr2_l, out_ihat, I_t, nullptr);

    finalize_kernel<<<1, 32>>>(out_scal);
    (void)in_sizes; (void)n_in; (void)out_size;
}